// round 3
// baseline (speedup 1.0000x reference)
#include <cuda_runtime.h>
#include <cstdint>

#define NNODES 100000
#define NEDGES 1600000
#define DIM 128
#define NGRAPHS 128
#define NLAYERS 3
#define BN_EPS 1e-5f

// ---------------- scratch (static device globals; no allocation) -------------
__device__ float g_h[(size_t)NNODES * DIM];      // GEMM2 output (pre-BN h)
__device__ float g_tmp[(size_t)NNODES * DIM];    // GEMM1 output
__device__ float g_sum[DIM];
__device__ float g_sumsq[DIM];
__device__ float g_scale[DIM];
__device__ float g_shift[DIM];

// CSR by destination
__device__ int g_cnt[NNODES];
__device__ int g_rowptr[NNODES + 1];
__device__ int g_cur[NNODES];
__device__ int g_srcbuf[NEDGES];

// ---------------- CSR construction -------------------------------------------
__global__ void k_zero_cnt() {
    int i = blockIdx.x * blockDim.x + threadIdx.x;
    int stride = gridDim.x * blockDim.x;
    for (int j = i; j < NNODES; j += stride) g_cnt[j] = 0;
}

__global__ void k_hist(const int* __restrict__ ei) {
    int i = blockIdx.x * blockDim.x + threadIdx.x;
    int stride = gridDim.x * blockDim.x;
    for (int e = i; e < NEDGES; e += stride)
        atomicAdd(&g_cnt[ei[NEDGES + e]], 1);
}

// single-block exclusive scan over g_cnt -> g_rowptr, g_cur
__global__ void k_scan() {
    __shared__ int warp_sums[32];
    __shared__ int carry;
    const int tid = threadIdx.x;
    const int lane = tid & 31;
    const int wid = tid >> 5;
    if (tid == 0) carry = 0;
    __syncthreads();
    for (int base = 0; base < NNODES; base += 1024) {
        int i = base + tid;
        int v = (i < NNODES) ? g_cnt[i] : 0;
        int x = v;
        #pragma unroll
        for (int o = 1; o < 32; o <<= 1) {
            int t = __shfl_up_sync(~0u, x, o);
            if (lane >= o) x += t;
        }
        if (lane == 31) warp_sums[wid] = x;
        __syncthreads();
        if (wid == 0) {
            int s = warp_sums[lane];
            #pragma unroll
            for (int o = 1; o < 32; o <<= 1) {
                int t = __shfl_up_sync(~0u, s, o);
                if (lane >= o) s += t;
            }
            warp_sums[lane] = s;
        }
        __syncthreads();
        int incl = x + (wid > 0 ? warp_sums[wid - 1] : 0);
        int excl = carry + incl - v;
        if (i < NNODES) { g_rowptr[i] = excl; g_cur[i] = excl; }
        __syncthreads();
        if (tid == 0) carry += warp_sums[31];
        __syncthreads();
    }
    if (tid == 0) g_rowptr[NNODES] = carry;
}

__global__ void k_fill(const int* __restrict__ ei) {
    int i = blockIdx.x * blockDim.x + threadIdx.x;
    int stride = gridDim.x * blockDim.x;
    for (int e = i; e < NEDGES; e += stride) {
        int d = ei[NEDGES + e];
        int pos = atomicAdd(&g_cur[d], 1);
        g_srcbuf[pos] = ei[e];
    }
}

// ---------------- common GEMM compute macro-ish helpers ----------------------
#define AS_PITCH 132
#define GEMM_SMEM ((DIM * DIM + 64 * AS_PITCH) * 4)

// ---------------- fused: aggregate (gather) + GEMM1 --------------------------
// out = relu( (z_self + sum_neighbors z) @ W1 + b1 )
__global__ void k_aggr_gemm1(const float* __restrict__ zin, int pin,
                             const float* __restrict__ W,
                             const float* __restrict__ bias,
                             float* __restrict__ out,
                             int nrows) {
    extern __shared__ float sm[];
    float* ws = sm;                 // 128*128
    float* as = sm + DIM * DIM;     // 64*132

    const int tid = threadIdx.x;
    const int lane = tid & 31;
    const int wid = tid >> 5;       // 0..7
    const int row0 = blockIdx.x * 64;

    // load W: 4096 float4, 16 per thread (overlaps with gather below)
    {
        const float4* Wv = (const float4*)W;
        float4* wv = (float4*)ws;
        #pragma unroll
        for (int i = 0; i < 16; i++) wv[tid + i * 256] = Wv[tid + i * 256];
    }

    // gather-aggregate A tile: warp handles 8 nodes, float4 per lane
    {
        const int c = lane * 4;
        #pragma unroll
        for (int i = 0; i < 8; i++) {
            const int r = wid * 8 + i;
            const int gr = row0 + r;
            float4 a0 = make_float4(0.f, 0.f, 0.f, 0.f);
            float4 a1 = a0, a2 = a0, a3 = a0;
            if (gr < nrows) {
                a0 = *(const float4*)(zin + (size_t)gr * pin + c);   // self
                const int beg = g_rowptr[gr];
                const int end = g_rowptr[gr + 1];
                int e = beg;
                for (; e + 4 <= end; e += 4) {
                    int s0 = g_srcbuf[e], s1 = g_srcbuf[e + 1];
                    int s2 = g_srcbuf[e + 2], s3 = g_srcbuf[e + 3];
                    float4 v0 = *(const float4*)(zin + (size_t)s0 * pin + c);
                    float4 v1 = *(const float4*)(zin + (size_t)s1 * pin + c);
                    float4 v2 = *(const float4*)(zin + (size_t)s2 * pin + c);
                    float4 v3 = *(const float4*)(zin + (size_t)s3 * pin + c);
                    a0.x += v0.x; a0.y += v0.y; a0.z += v0.z; a0.w += v0.w;
                    a1.x += v1.x; a1.y += v1.y; a1.z += v1.z; a1.w += v1.w;
                    a2.x += v2.x; a2.y += v2.y; a2.z += v2.z; a2.w += v2.w;
                    a3.x += v3.x; a3.y += v3.y; a3.z += v3.z; a3.w += v3.w;
                }
                for (; e < end; e++) {
                    int s = g_srcbuf[e];
                    float4 v = *(const float4*)(zin + (size_t)s * pin + c);
                    a0.x += v.x; a0.y += v.y; a0.z += v.z; a0.w += v.w;
                }
                a0.x += a1.x + a2.x + a3.x;
                a0.y += a1.y + a2.y + a3.y;
                a0.z += a1.z + a2.z + a3.z;
                a0.w += a1.w + a2.w + a3.w;
            }
            *(float4*)(as + r * AS_PITCH + c) = a0;
        }
    }
    __syncthreads();

    const int c0 = (tid & 15) * 4;
    const int r0 = (tid >> 4) * 4;

    unsigned long long acc[4][4];
    #pragma unroll
    for (int r = 0; r < 4; r++)
        #pragma unroll
        for (int c = 0; c < 4; c++) acc[r][c] = 0ULL;

    #pragma unroll 4
    for (int k0 = 0; k0 < DIM; k0 += 4) {
        float4 a4[4];
        #pragma unroll
        for (int r = 0; r < 4; r++)
            a4[r] = *(const float4*)(as + (r0 + r) * AS_PITCH + k0);
        #pragma unroll
        for (int kk = 0; kk < 4; kk++) {
            const float* wrow = ws + (k0 + kk) * DIM;
            ulonglong2 w0 = *(const ulonglong2*)(wrow + c0);
            ulonglong2 w1 = *(const ulonglong2*)(wrow + c0 + 64);
            #pragma unroll
            for (int r = 0; r < 4; r++) {
                float a = (&a4[r].x)[kk];
                unsigned long long aa;
                asm("mov.b64 %0, {%1, %1};" : "=l"(aa) : "f"(a));
                asm("fma.rn.f32x2 %0, %1, %2, %0;" : "+l"(acc[r][0]) : "l"(aa), "l"(w0.x));
                asm("fma.rn.f32x2 %0, %1, %2, %0;" : "+l"(acc[r][1]) : "l"(aa), "l"(w0.y));
                asm("fma.rn.f32x2 %0, %1, %2, %0;" : "+l"(acc[r][2]) : "l"(aa), "l"(w1.x));
                asm("fma.rn.f32x2 %0, %1, %2, %0;" : "+l"(acc[r][3]) : "l"(aa), "l"(w1.y));
            }
        }
    }

    float b0[4], b1[4];
    #pragma unroll
    for (int j = 0; j < 4; j++) {
        b0[j] = __ldg(&bias[c0 + j]);
        b1[j] = __ldg(&bias[c0 + 64 + j]);
    }
    #pragma unroll
    for (int r = 0; r < 4; r++) {
        int gr = row0 + r0 + r;
        if (gr >= nrows) break;
        float o0[4], o1[4];
        #pragma unroll
        for (int c = 0; c < 2; c++) {
            float lo, hi;
            asm("mov.b64 {%0, %1}, %2;" : "=f"(lo), "=f"(hi) : "l"(acc[r][c]));
            o0[2 * c]     = fmaxf(lo + b0[2 * c], 0.f);
            o0[2 * c + 1] = fmaxf(hi + b0[2 * c + 1], 0.f);
            asm("mov.b64 {%0, %1}, %2;" : "=f"(lo), "=f"(hi) : "l"(acc[r][c + 2]));
            o1[2 * c]     = fmaxf(lo + b1[2 * c], 0.f);
            o1[2 * c + 1] = fmaxf(hi + b1[2 * c + 1], 0.f);
        }
        *(float4*)(out + (size_t)gr * DIM + c0)      = make_float4(o0[0], o0[1], o0[2], o0[3]);
        *(float4*)(out + (size_t)gr * DIM + c0 + 64) = make_float4(o1[0], o1[1], o1[2], o1[3]);
    }
}

// ---------------- GEMM2 + fused BN statistics ---------------------------------
// out = relu(A @ W + bias); accumulates per-feature sum & sumsq into g_sum/g_sumsq
__global__ void k_gemm2_stats(const float* __restrict__ A,
                              const float* __restrict__ W,
                              const float* __restrict__ bias,
                              float* __restrict__ out,
                              int nrows) {
    extern __shared__ float sm[];
    float* ws = sm;                 // 128*128
    float* as = sm + DIM * DIM;     // 64*132 (reused for stats reduction)

    const int tid = threadIdx.x;
    const int row0 = blockIdx.x * 64;

    {
        const float4* Wv = (const float4*)W;
        float4* wv = (float4*)ws;
        #pragma unroll
        for (int i = 0; i < 16; i++) wv[tid + i * 256] = Wv[tid + i * 256];
    }
    {
        #pragma unroll
        for (int i = 0; i < 8; i++) {
            int fi = tid + i * 256;
            int r = fi >> 5;
            int c = (fi & 31) << 2;
            int gr = row0 + r;
            float4 v = make_float4(0.f, 0.f, 0.f, 0.f);
            if (gr < nrows) v = *(const float4*)(A + (size_t)gr * DIM + c);
            *(float4*)(as + r * AS_PITCH + c) = v;
        }
    }
    __syncthreads();

    const int cg = tid & 15;
    const int rg = tid >> 4;
    const int c0 = cg * 4;
    const int r0 = rg * 4;

    unsigned long long acc[4][4];
    #pragma unroll
    for (int r = 0; r < 4; r++)
        #pragma unroll
        for (int c = 0; c < 4; c++) acc[r][c] = 0ULL;

    #pragma unroll 4
    for (int k0 = 0; k0 < DIM; k0 += 4) {
        float4 a4[4];
        #pragma unroll
        for (int r = 0; r < 4; r++)
            a4[r] = *(const float4*)(as + (r0 + r) * AS_PITCH + k0);
        #pragma unroll
        for (int kk = 0; kk < 4; kk++) {
            const float* wrow = ws + (k0 + kk) * DIM;
            ulonglong2 w0 = *(const ulonglong2*)(wrow + c0);
            ulonglong2 w1 = *(const ulonglong2*)(wrow + c0 + 64);
            #pragma unroll
            for (int r = 0; r < 4; r++) {
                float a = (&a4[r].x)[kk];
                unsigned long long aa;
                asm("mov.b64 %0, {%1, %1};" : "=l"(aa) : "f"(a));
                asm("fma.rn.f32x2 %0, %1, %2, %0;" : "+l"(acc[r][0]) : "l"(aa), "l"(w0.x));
                asm("fma.rn.f32x2 %0, %1, %2, %0;" : "+l"(acc[r][1]) : "l"(aa), "l"(w0.y));
                asm("fma.rn.f32x2 %0, %1, %2, %0;" : "+l"(acc[r][2]) : "l"(aa), "l"(w1.x));
                asm("fma.rn.f32x2 %0, %1, %2, %0;" : "+l"(acc[r][3]) : "l"(aa), "l"(w1.y));
            }
        }
    }

    float b0[4], b1[4];
    #pragma unroll
    for (int j = 0; j < 4; j++) {
        b0[j] = __ldg(&bias[c0 + j]);
        b1[j] = __ldg(&bias[c0 + 64 + j]);
    }

    float ps0[4] = {0.f, 0.f, 0.f, 0.f}, pq0[4] = {0.f, 0.f, 0.f, 0.f};
    float ps1[4] = {0.f, 0.f, 0.f, 0.f}, pq1[4] = {0.f, 0.f, 0.f, 0.f};

    #pragma unroll
    for (int r = 0; r < 4; r++) {
        int gr = row0 + r0 + r;
        if (gr >= nrows) break;
        float o0[4], o1[4];
        #pragma unroll
        for (int c = 0; c < 2; c++) {
            float lo, hi;
            asm("mov.b64 {%0, %1}, %2;" : "=f"(lo), "=f"(hi) : "l"(acc[r][c]));
            o0[2 * c]     = fmaxf(lo + b0[2 * c], 0.f);
            o0[2 * c + 1] = fmaxf(hi + b0[2 * c + 1], 0.f);
            asm("mov.b64 {%0, %1}, %2;" : "=f"(lo), "=f"(hi) : "l"(acc[r][c + 2]));
            o1[2 * c]     = fmaxf(lo + b1[2 * c], 0.f);
            o1[2 * c + 1] = fmaxf(hi + b1[2 * c + 1], 0.f);
        }
        #pragma unroll
        for (int j = 0; j < 4; j++) {
            ps0[j] += o0[j]; pq0[j] += o0[j] * o0[j];
            ps1[j] += o1[j]; pq1[j] += o1[j] * o1[j];
        }
        *(float4*)(out + (size_t)gr * DIM + c0)      = make_float4(o0[0], o0[1], o0[2], o0[3]);
        *(float4*)(out + (size_t)gr * DIM + c0 + 64) = make_float4(o1[0], o1[1], o1[2], o1[3]);
    }

    // block-level stats reduction (reuse as[] region: 2 * 16 * 132 floats)
    __syncthreads();   // everyone done reading as
    float* s_sum = as;                  // [16][132]
    float* s_sq  = as + 16 * 132;       // [16][132]
    #pragma unroll
    for (int j = 0; j < 4; j++) {
        s_sum[rg * 132 + c0 + j]      = ps0[j];
        s_sum[rg * 132 + c0 + 64 + j] = ps1[j];
        s_sq[rg * 132 + c0 + j]       = pq0[j];
        s_sq[rg * 132 + c0 + 64 + j]  = pq1[j];
    }
    __syncthreads();
    if (tid < 128) {
        float t = 0.f;
        #pragma unroll
        for (int g = 0; g < 16; g++) t += s_sum[g * 132 + tid];
        atomicAdd(&g_sum[tid], t);
    } else {
        int f = tid - 128;
        float t = 0.f;
        #pragma unroll
        for (int g = 0; g < 16; g++) t += s_sq[g * 132 + f];
        atomicAdd(&g_sumsq[f], t);
    }
}

// ---------------- batchnorm micro kernels --------------------------------------
__global__ void k_zero_stats() {
    if (threadIdx.x < DIM) {
        g_sum[threadIdx.x] = 0.f;
        g_sumsq[threadIdx.x] = 0.f;
    }
}

__global__ void k_finalize(const float* __restrict__ gamma,
                           const float* __restrict__ beta) {
    int f = threadIdx.x;
    float mean = g_sum[f] * (1.0f / NNODES);
    float var = g_sumsq[f] * (1.0f / NNODES) - mean * mean;
    float inv = rsqrtf(var + BN_EPS);
    float sc = gamma[f] * inv;
    g_scale[f] = sc;
    g_shift[f] = beta[f] - mean * sc;
}

// ---------------- normalize + z_cat slice + graph add-pool --------------------
__global__ void k_zero_gcat(float* gcat) {
    int i = blockIdx.x * blockDim.x + threadIdx.x;
    if (i < NGRAPHS * NLAYERS * DIM) gcat[i] = 0.f;
}

#define NP_CH 512
__global__ void k_norm_pool(const float* __restrict__ h,
                            const int* __restrict__ batch,
                            float* __restrict__ zout,
                            float* __restrict__ gout) {
    const int f = threadIdx.x & 127;
    const int ln = threadIdx.x >> 7;
    const int r0 = blockIdx.x * NP_CH;
    const int rend = min(r0 + NP_CH, NNODES);
    const float sc = g_scale[f];
    const float sh = g_shift[f];
    float acc = 0.f;
    int cur = -1;
    for (int r = r0 + ln; r < rend; r += 4) {
        float v = fmaf(h[(size_t)r * DIM + f], sc, sh);
        zout[(size_t)r * (NLAYERS * DIM) + f] = v;
        int b = batch[r];
        if (b != cur) {
            if (cur >= 0) atomicAdd(&gout[(size_t)cur * (NLAYERS * DIM) + f], acc);
            cur = b;
            acc = v;
        } else {
            acc += v;
        }
    }
    if (cur >= 0) atomicAdd(&gout[(size_t)cur * (NLAYERS * DIM) + f], acc);
}

// ---------------- launch -------------------------------------------------------
extern "C" void kernel_launch(void* const* d_in, const int* in_sizes, int n_in,
                              void* d_out, int out_size) {
    const float* x     = (const float*)d_in[0];
    const int*   ei    = (const int*)d_in[1];
    const int*   batch = (const int*)d_in[2];
    const float* W1    = (const float*)d_in[3];
    const float* b1    = (const float*)d_in[4];
    const float* W2    = (const float*)d_in[5];
    const float* b2    = (const float*)d_in[6];
    const float* gamma = (const float*)d_in[7];
    const float* beta  = (const float*)d_in[8];

    float* z_cat = (float*)d_out;                               // [N, 384]
    float* g_cat = z_cat + (size_t)NNODES * NLAYERS * DIM;      // [128, 384]

    cudaFuncSetAttribute(k_aggr_gemm1, cudaFuncAttributeMaxDynamicSharedMemorySize,
                         GEMM_SMEM);
    cudaFuncSetAttribute(k_gemm2_stats, cudaFuncAttributeMaxDynamicSharedMemorySize,
                         GEMM_SMEM);

    float* hbuf;  cudaGetSymbolAddress((void**)&hbuf, g_h);
    float* tmp;   cudaGetSymbolAddress((void**)&tmp, g_tmp);

    // CSR build (recomputed each call; deterministic)
    k_zero_cnt<<<128, 512>>>();
    k_hist<<<1024, 512>>>(ei);
    k_scan<<<1, 1024>>>();
    k_fill<<<1024, 512>>>(ei);

    k_zero_gcat<<<(NGRAPHS * NLAYERS * DIM + 255) / 256, 256>>>(g_cat);

    const int gemm_grid = (NNODES + 63) / 64;
    const int np_grid   = (NNODES + NP_CH - 1) / NP_CH;

    for (int l = 0; l < NLAYERS; l++) {
        const float* zin = (l == 0) ? x : (z_cat + (size_t)(l - 1) * DIM);
        const int pin = (l == 0) ? DIM : (NLAYERS * DIM);

        k_zero_stats<<<1, 128>>>();
        k_aggr_gemm1<<<gemm_grid, 256, GEMM_SMEM>>>(zin, pin,
                                                    W1 + (size_t)l * DIM * DIM,
                                                    b1 + (size_t)l * DIM, tmp, NNODES);
        k_gemm2_stats<<<gemm_grid, 256, GEMM_SMEM>>>(tmp,
                                                     W2 + (size_t)l * DIM * DIM,
                                                     b2 + (size_t)l * DIM, hbuf, NNODES);
        k_finalize<<<1, 128>>>(gamma + (size_t)l * DIM, beta + (size_t)l * DIM);
        k_norm_pool<<<np_grid, 512>>>(hbuf, batch,
                                      z_cat + (size_t)l * DIM,
                                      g_cat + (size_t)l * DIM);
    }
}

// round 4
// speedup vs baseline: 1.1573x; 1.1573x over previous
#include <cuda_runtime.h>
#include <cstdint>

#define NNODES 100000
#define NEDGES 1600000
#define DIM 128
#define NGRAPHS 128
#define NLAYERS 3
#define BN_EPS 1e-5f
#define NCHUNK ((NNODES + 1023) / 1024)

// ---------------- scratch (static device globals; no allocation) -------------
__device__ float g_aggr[(size_t)NNODES * DIM];   // aggregate out; reused as h (GEMM2 out)
__device__ float g_tmp[(size_t)NNODES * DIM];    // GEMM1 output
__device__ float g_sum[DIM];
__device__ float g_sumsq[DIM];
__device__ float g_scale[DIM];
__device__ float g_shift[DIM];

// CSR by destination
__device__ int g_cnt[NNODES];
__device__ int g_rowptr[NNODES + 1];
__device__ int g_cur[NNODES];
__device__ int g_srcbuf[NEDGES];
__device__ int g_csum[NCHUNK];   // per-chunk sums
__device__ int g_coff[NCHUNK];   // per-chunk exclusive offsets

// ---------------- CSR construction -------------------------------------------
__global__ void k_zero_cnt() {
    int i = blockIdx.x * blockDim.x + threadIdx.x;
    int stride = gridDim.x * blockDim.x;
    for (int j = i; j < NNODES; j += stride) g_cnt[j] = 0;
    if (blockIdx.x == 0 && threadIdx.x < DIM) {
        g_sum[threadIdx.x] = 0.f;
        g_sumsq[threadIdx.x] = 0.f;
    }
}

__global__ void k_hist(const int* __restrict__ ei) {
    int i = blockIdx.x * blockDim.x + threadIdx.x;
    int stride = gridDim.x * blockDim.x;
    for (int e = i; e < NEDGES; e += stride)
        atomicAdd(&g_cnt[ei[NEDGES + e]], 1);
}

// chunked scan, pass 1: per-chunk sums (grid = NCHUNK, block = 1024)
__global__ void k_chunksum() {
    __shared__ int wsum[32];
    int i = blockIdx.x * 1024 + threadIdx.x;
    int v = (i < NNODES) ? g_cnt[i] : 0;
    #pragma unroll
    for (int o = 16; o > 0; o >>= 1) v += __shfl_down_sync(~0u, v, o);
    if ((threadIdx.x & 31) == 0) wsum[threadIdx.x >> 5] = v;
    __syncthreads();
    if (threadIdx.x < 32) {
        int s = wsum[threadIdx.x];
        #pragma unroll
        for (int o = 16; o > 0; o >>= 1) s += __shfl_down_sync(~0u, s, o);
        if (threadIdx.x == 0) g_csum[blockIdx.x] = s;
    }
}

// pass 2: scan NCHUNK (=98) values in one block of 128 threads
__global__ void k_scanchunks() {
    __shared__ int sh[4];
    const int tid = threadIdx.x;
    const int lane = tid & 31;
    const int wid = tid >> 5;
    int v = (tid < NCHUNK) ? g_csum[tid] : 0;
    int x = v;
    #pragma unroll
    for (int o = 1; o < 32; o <<= 1) {
        int t = __shfl_up_sync(~0u, x, o);
        if (lane >= o) x += t;
    }
    if (lane == 31) sh[wid] = x;
    __syncthreads();
    int base = 0;
    #pragma unroll
    for (int w = 0; w < 4; w++) if (w < wid) base += sh[w];
    int excl = base + x - v;
    if (tid < NCHUNK) g_coff[tid] = excl;
    if (tid == 127) g_rowptr[NNODES] = base + x;   // total
}

// pass 3: per-chunk exclusive scan + offset, write rowptr & cur
__global__ void k_scanwrite() {
    __shared__ int wsum[32];
    const int tid = threadIdx.x;
    const int lane = tid & 31;
    const int wid = tid >> 5;
    int i = blockIdx.x * 1024 + tid;
    int v = (i < NNODES) ? g_cnt[i] : 0;
    int x = v;
    #pragma unroll
    for (int o = 1; o < 32; o <<= 1) {
        int t = __shfl_up_sync(~0u, x, o);
        if (lane >= o) x += t;
    }
    if (lane == 31) wsum[wid] = x;
    __syncthreads();
    if (wid == 0) {
        int s = (lane < 32) ? wsum[lane] : 0;
        #pragma unroll
        for (int o = 1; o < 32; o <<= 1) {
            int t = __shfl_up_sync(~0u, s, o);
            if (lane >= o) s += t;
        }
        wsum[lane] = s;
    }
    __syncthreads();
    int excl = g_coff[blockIdx.x] + x - v + (wid > 0 ? wsum[wid - 1] : 0);
    if (i < NNODES) { g_rowptr[i] = excl; g_cur[i] = excl; }
}

__global__ void k_fill(const int* __restrict__ ei) {
    int i = blockIdx.x * blockDim.x + threadIdx.x;
    int stride = gridDim.x * blockDim.x;
    for (int e = i; e < NEDGES; e += stride) {
        int d = ei[NEDGES + e];
        int pos = atomicAdd(&g_cur[d], 1);
        g_srcbuf[pos] = ei[e];
    }
}

// ---------------- gather aggregation: aggr[n] = z[n] + sum_{j->n} z[j] --------
__global__ void k_aggregate(const float* __restrict__ zin, int pin) {
    const int lane = threadIdx.x & 31;
    const int w = (blockIdx.x * blockDim.x + threadIdx.x) >> 5;
    if (w >= NNODES) return;
    const int c = lane * 4;
    const int beg = g_rowptr[w];
    const int end = g_rowptr[w + 1];
    float4 a0 = *(const float4*)(zin + (size_t)w * pin + c);   // self
    float4 a1 = make_float4(0.f, 0.f, 0.f, 0.f);
    float4 a2 = a1, a3 = a1;
    int e = beg;
    for (; e + 4 <= end; e += 4) {
        int s0 = g_srcbuf[e], s1 = g_srcbuf[e + 1];
        int s2 = g_srcbuf[e + 2], s3 = g_srcbuf[e + 3];
        float4 v0 = *(const float4*)(zin + (size_t)s0 * pin + c);
        float4 v1 = *(const float4*)(zin + (size_t)s1 * pin + c);
        float4 v2 = *(const float4*)(zin + (size_t)s2 * pin + c);
        float4 v3 = *(const float4*)(zin + (size_t)s3 * pin + c);
        a0.x += v0.x; a0.y += v0.y; a0.z += v0.z; a0.w += v0.w;
        a1.x += v1.x; a1.y += v1.y; a1.z += v1.z; a1.w += v1.w;
        a2.x += v2.x; a2.y += v2.y; a2.z += v2.z; a2.w += v2.w;
        a3.x += v3.x; a3.y += v3.y; a3.z += v3.z; a3.w += v3.w;
    }
    for (; e < end; e++) {
        int s = g_srcbuf[e];
        float4 v = *(const float4*)(zin + (size_t)s * pin + c);
        a0.x += v.x; a0.y += v.y; a0.z += v.z; a0.w += v.w;
    }
    a0.x += a1.x + a2.x + a3.x;
    a0.y += a1.y + a2.y + a3.y;
    a0.z += a1.z + a2.z + a3.z;
    a0.w += a1.w + a2.w + a3.w;
    *(float4*)(g_aggr + (size_t)w * DIM + c) = a0;
}

// ---------------- GEMM kernels ------------------------------------------------
#define AS_PITCH 132
#define GEMM_SMEM ((DIM * DIM + 64 * AS_PITCH) * 4)

// GEMM1: out = relu(A @ W + bias)
__global__ void k_gemm(const float* __restrict__ A,
                       const float* __restrict__ W,
                       const float* __restrict__ bias,
                       float* __restrict__ out,
                       int nrows) {
    extern __shared__ float sm[];
    float* ws = sm;
    float* as = sm + DIM * DIM;

    const int tid = threadIdx.x;
    const int row0 = blockIdx.x * 64;

    {
        const float4* Wv = (const float4*)W;
        float4* wv = (float4*)ws;
        #pragma unroll
        for (int i = 0; i < 16; i++) wv[tid + i * 256] = Wv[tid + i * 256];
    }
    {
        #pragma unroll
        for (int i = 0; i < 8; i++) {
            int fi = tid + i * 256;
            int r = fi >> 5;
            int c = (fi & 31) << 2;
            int gr = row0 + r;
            float4 v = make_float4(0.f, 0.f, 0.f, 0.f);
            if (gr < nrows) v = *(const float4*)(A + (size_t)gr * DIM + c);
            *(float4*)(as + r * AS_PITCH + c) = v;
        }
    }
    __syncthreads();

    const int c0 = (tid & 15) * 4;
    const int r0 = (tid >> 4) * 4;

    unsigned long long acc[4][4];
    #pragma unroll
    for (int r = 0; r < 4; r++)
        #pragma unroll
        for (int c = 0; c < 4; c++) acc[r][c] = 0ULL;

    #pragma unroll 4
    for (int k0 = 0; k0 < DIM; k0 += 4) {
        float4 a4[4];
        #pragma unroll
        for (int r = 0; r < 4; r++)
            a4[r] = *(const float4*)(as + (r0 + r) * AS_PITCH + k0);
        #pragma unroll
        for (int kk = 0; kk < 4; kk++) {
            const float* wrow = ws + (k0 + kk) * DIM;
            ulonglong2 w0 = *(const ulonglong2*)(wrow + c0);
            ulonglong2 w1 = *(const ulonglong2*)(wrow + c0 + 64);
            #pragma unroll
            for (int r = 0; r < 4; r++) {
                float a = (&a4[r].x)[kk];
                unsigned long long aa;
                asm("mov.b64 %0, {%1, %1};" : "=l"(aa) : "f"(a));
                asm("fma.rn.f32x2 %0, %1, %2, %0;" : "+l"(acc[r][0]) : "l"(aa), "l"(w0.x));
                asm("fma.rn.f32x2 %0, %1, %2, %0;" : "+l"(acc[r][1]) : "l"(aa), "l"(w0.y));
                asm("fma.rn.f32x2 %0, %1, %2, %0;" : "+l"(acc[r][2]) : "l"(aa), "l"(w1.x));
                asm("fma.rn.f32x2 %0, %1, %2, %0;" : "+l"(acc[r][3]) : "l"(aa), "l"(w1.y));
            }
        }
    }

    float b0[4], b1[4];
    #pragma unroll
    for (int j = 0; j < 4; j++) {
        b0[j] = __ldg(&bias[c0 + j]);
        b1[j] = __ldg(&bias[c0 + 64 + j]);
    }
    #pragma unroll
    for (int r = 0; r < 4; r++) {
        int gr = row0 + r0 + r;
        if (gr >= nrows) break;
        float o0[4], o1[4];
        #pragma unroll
        for (int c = 0; c < 2; c++) {
            float lo, hi;
            asm("mov.b64 {%0, %1}, %2;" : "=f"(lo), "=f"(hi) : "l"(acc[r][c]));
            o0[2 * c]     = fmaxf(lo + b0[2 * c], 0.f);
            o0[2 * c + 1] = fmaxf(hi + b0[2 * c + 1], 0.f);
            asm("mov.b64 {%0, %1}, %2;" : "=f"(lo), "=f"(hi) : "l"(acc[r][c + 2]));
            o1[2 * c]     = fmaxf(lo + b1[2 * c], 0.f);
            o1[2 * c + 1] = fmaxf(hi + b1[2 * c + 1], 0.f);
        }
        *(float4*)(out + (size_t)gr * DIM + c0)      = make_float4(o0[0], o0[1], o0[2], o0[3]);
        *(float4*)(out + (size_t)gr * DIM + c0 + 64) = make_float4(o1[0], o1[1], o1[2], o1[3]);
    }
}

// GEMM2 + fused BN statistics
__global__ void k_gemm2_stats(const float* __restrict__ A,
                              const float* __restrict__ W,
                              const float* __restrict__ bias,
                              float* __restrict__ out,
                              int nrows) {
    extern __shared__ float sm[];
    float* ws = sm;
    float* as = sm + DIM * DIM;

    const int tid = threadIdx.x;
    const int row0 = blockIdx.x * 64;

    {
        const float4* Wv = (const float4*)W;
        float4* wv = (float4*)ws;
        #pragma unroll
        for (int i = 0; i < 16; i++) wv[tid + i * 256] = Wv[tid + i * 256];
    }
    {
        #pragma unroll
        for (int i = 0; i < 8; i++) {
            int fi = tid + i * 256;
            int r = fi >> 5;
            int c = (fi & 31) << 2;
            int gr = row0 + r;
            float4 v = make_float4(0.f, 0.f, 0.f, 0.f);
            if (gr < nrows) v = *(const float4*)(A + (size_t)gr * DIM + c);
            *(float4*)(as + r * AS_PITCH + c) = v;
        }
    }
    __syncthreads();

    const int cg = tid & 15;
    const int rg = tid >> 4;
    const int c0 = cg * 4;
    const int r0 = rg * 4;

    unsigned long long acc[4][4];
    #pragma unroll
    for (int r = 0; r < 4; r++)
        #pragma unroll
        for (int c = 0; c < 4; c++) acc[r][c] = 0ULL;

    #pragma unroll 4
    for (int k0 = 0; k0 < DIM; k0 += 4) {
        float4 a4[4];
        #pragma unroll
        for (int r = 0; r < 4; r++)
            a4[r] = *(const float4*)(as + (r0 + r) * AS_PITCH + k0);
        #pragma unroll
        for (int kk = 0; kk < 4; kk++) {
            const float* wrow = ws + (k0 + kk) * DIM;
            ulonglong2 w0 = *(const ulonglong2*)(wrow + c0);
            ulonglong2 w1 = *(const ulonglong2*)(wrow + c0 + 64);
            #pragma unroll
            for (int r = 0; r < 4; r++) {
                float a = (&a4[r].x)[kk];
                unsigned long long aa;
                asm("mov.b64 %0, {%1, %1};" : "=l"(aa) : "f"(a));
                asm("fma.rn.f32x2 %0, %1, %2, %0;" : "+l"(acc[r][0]) : "l"(aa), "l"(w0.x));
                asm("fma.rn.f32x2 %0, %1, %2, %0;" : "+l"(acc[r][1]) : "l"(aa), "l"(w0.y));
                asm("fma.rn.f32x2 %0, %1, %2, %0;" : "+l"(acc[r][2]) : "l"(aa), "l"(w1.x));
                asm("fma.rn.f32x2 %0, %1, %2, %0;" : "+l"(acc[r][3]) : "l"(aa), "l"(w1.y));
            }
        }
    }

    float b0[4], b1[4];
    #pragma unroll
    for (int j = 0; j < 4; j++) {
        b0[j] = __ldg(&bias[c0 + j]);
        b1[j] = __ldg(&bias[c0 + 64 + j]);
    }

    float ps0[4] = {0.f, 0.f, 0.f, 0.f}, pq0[4] = {0.f, 0.f, 0.f, 0.f};
    float ps1[4] = {0.f, 0.f, 0.f, 0.f}, pq1[4] = {0.f, 0.f, 0.f, 0.f};

    #pragma unroll
    for (int r = 0; r < 4; r++) {
        int gr = row0 + r0 + r;
        if (gr >= nrows) break;
        float o0[4], o1[4];
        #pragma unroll
        for (int c = 0; c < 2; c++) {
            float lo, hi;
            asm("mov.b64 {%0, %1}, %2;" : "=f"(lo), "=f"(hi) : "l"(acc[r][c]));
            o0[2 * c]     = fmaxf(lo + b0[2 * c], 0.f);
            o0[2 * c + 1] = fmaxf(hi + b0[2 * c + 1], 0.f);
            asm("mov.b64 {%0, %1}, %2;" : "=f"(lo), "=f"(hi) : "l"(acc[r][c + 2]));
            o1[2 * c]     = fmaxf(lo + b1[2 * c], 0.f);
            o1[2 * c + 1] = fmaxf(hi + b1[2 * c + 1], 0.f);
        }
        #pragma unroll
        for (int j = 0; j < 4; j++) {
            ps0[j] += o0[j]; pq0[j] += o0[j] * o0[j];
            ps1[j] += o1[j]; pq1[j] += o1[j] * o1[j];
        }
        *(float4*)(out + (size_t)gr * DIM + c0)      = make_float4(o0[0], o0[1], o0[2], o0[3]);
        *(float4*)(out + (size_t)gr * DIM + c0 + 64) = make_float4(o1[0], o1[1], o1[2], o1[3]);
    }

    // block-level stats reduction in smem (reuse as[])
    __syncthreads();
    float* s_sum = as;                  // [16][132]
    float* s_sq  = as + 16 * 132;       // [16][132]
    #pragma unroll
    for (int j = 0; j < 4; j++) {
        s_sum[rg * 132 + c0 + j]      = ps0[j];
        s_sum[rg * 132 + c0 + 64 + j] = ps1[j];
        s_sq[rg * 132 + c0 + j]       = pq0[j];
        s_sq[rg * 132 + c0 + 64 + j]  = pq1[j];
    }
    __syncthreads();
    if (tid < 128) {
        float t = 0.f;
        #pragma unroll
        for (int g = 0; g < 16; g++) t += s_sum[g * 132 + tid];
        atomicAdd(&g_sum[tid], t);
    } else {
        int f = tid - 128;
        float t = 0.f;
        #pragma unroll
        for (int g = 0; g < 16; g++) t += s_sq[g * 132 + f];
        atomicAdd(&g_sumsq[f], t);
    }
}

// ---------------- finalize BN (and zero stats for next layer) -----------------
__global__ void k_finalize(const float* __restrict__ gamma,
                           const float* __restrict__ beta) {
    int f = threadIdx.x;
    float mean = g_sum[f] * (1.0f / NNODES);
    float var = g_sumsq[f] * (1.0f / NNODES) - mean * mean;
    float inv = rsqrtf(var + BN_EPS);
    float sc = gamma[f] * inv;
    g_scale[f] = sc;
    g_shift[f] = beta[f] - mean * sc;
    g_sum[f] = 0.f;      // ready for next layer
    g_sumsq[f] = 0.f;
}

// ---------------- normalize + z_cat slice + graph add-pool --------------------
__global__ void k_zero_gcat(float* gcat) {
    int i = blockIdx.x * blockDim.x + threadIdx.x;
    if (i < NGRAPHS * NLAYERS * DIM) gcat[i] = 0.f;
}

#define NP_CH 512
__global__ void k_norm_pool(const float* __restrict__ h,
                            const int* __restrict__ batch,
                            float* __restrict__ zout,
                            float* __restrict__ gout) {
    const int f = threadIdx.x & 127;
    const int ln = threadIdx.x >> 7;
    const int r0 = blockIdx.x * NP_CH;
    const int rend = min(r0 + NP_CH, NNODES);
    const float sc = g_scale[f];
    const float sh = g_shift[f];
    float acc = 0.f;
    int cur = -1;
    for (int r = r0 + ln; r < rend; r += 4) {
        float v = fmaf(h[(size_t)r * DIM + f], sc, sh);
        zout[(size_t)r * (NLAYERS * DIM) + f] = v;
        int b = batch[r];
        if (b != cur) {
            if (cur >= 0) atomicAdd(&gout[(size_t)cur * (NLAYERS * DIM) + f], acc);
            cur = b;
            acc = v;
        } else {
            acc += v;
        }
    }
    if (cur >= 0) atomicAdd(&gout[(size_t)cur * (NLAYERS * DIM) + f], acc);
}

// ---------------- launch -------------------------------------------------------
extern "C" void kernel_launch(void* const* d_in, const int* in_sizes, int n_in,
                              void* d_out, int out_size) {
    const float* x     = (const float*)d_in[0];
    const int*   ei    = (const int*)d_in[1];
    const int*   batch = (const int*)d_in[2];
    const float* W1    = (const float*)d_in[3];
    const float* b1    = (const float*)d_in[4];
    const float* W2    = (const float*)d_in[5];
    const float* b2    = (const float*)d_in[6];
    const float* gamma = (const float*)d_in[7];
    const float* beta  = (const float*)d_in[8];

    float* z_cat = (float*)d_out;                               // [N, 384]
    float* g_cat = z_cat + (size_t)NNODES * NLAYERS * DIM;      // [128, 384]

    cudaFuncSetAttribute(k_gemm, cudaFuncAttributeMaxDynamicSharedMemorySize,
                         GEMM_SMEM);
    cudaFuncSetAttribute(k_gemm2_stats, cudaFuncAttributeMaxDynamicSharedMemorySize,
                         GEMM_SMEM);

    float* aggr;  cudaGetSymbolAddress((void**)&aggr, g_aggr);
    float* tmp;   cudaGetSymbolAddress((void**)&tmp, g_tmp);

    // CSR build
    k_zero_cnt<<<128, 512>>>();                       // also zeroes BN stats
    k_hist<<<1024, 512>>>(ei);
    k_chunksum<<<NCHUNK, 1024>>>();
    k_scanchunks<<<1, 128>>>();
    k_scanwrite<<<NCHUNK, 1024>>>();
    k_fill<<<1024, 512>>>(ei);

    k_zero_gcat<<<(NGRAPHS * NLAYERS * DIM + 255) / 256, 256>>>(g_cat);

    const int gemm_grid = (NNODES + 63) / 64;
    const int np_grid   = (NNODES + NP_CH - 1) / NP_CH;
    const int agg_grid  = (NNODES * 32 + 255) / 256;   // warp per node

    for (int l = 0; l < NLAYERS; l++) {
        const float* zin = (l == 0) ? x : (z_cat + (size_t)(l - 1) * DIM);
        const int pin = (l == 0) ? DIM : (NLAYERS * DIM);

        k_aggregate<<<agg_grid, 256>>>(zin, pin);
        k_gemm<<<gemm_grid, 256, GEMM_SMEM>>>(aggr,
                                              W1 + (size_t)l * DIM * DIM,
                                              b1 + (size_t)l * DIM, tmp, NNODES);
        k_gemm2_stats<<<gemm_grid, 256, GEMM_SMEM>>>(tmp,
                                                     W2 + (size_t)l * DIM * DIM,
                                                     b2 + (size_t)l * DIM, aggr, NNODES);
        k_finalize<<<1, 128>>>(gamma + (size_t)l * DIM, beta + (size_t)l * DIM);
        k_norm_pool<<<np_grid, 512>>>(aggr, batch,
                                      z_cat + (size_t)l * DIM,
                                      g_cat + (size_t)l * DIM);
    }
}

// round 6
// speedup vs baseline: 1.3250x; 1.1449x over previous
#include <cuda_runtime.h>
#include <cuda_bf16.h>
#include <cstdint>

#define NNODES 100000
#define NEDGES 1600000
#define DIM 128
#define NGRAPHS 128
#define NLAYERS 3
#define BN_EPS 1e-5f
#define NCHUNK ((NNODES + 1023) / 1024)
#define NTILES ((NNODES + 127) / 128)
#define NROWS_PAD (NTILES * 128)

// ---------------- scratch (static device globals; no allocation) -------------
__device__ float g_aggr[(size_t)NNODES * DIM];   // aggregate out (GEMM1 A, fp32)
__device__ float g_h[(size_t)NNODES * DIM];      // GEMM2 out (pre-BN h, fp32)
__device__ float g_sum[DIM];
__device__ float g_sumsq[DIM];
__device__ float g_scale[DIM];
__device__ float g_shift[DIM];

// bf16 hi/lo intermediates (GEMM1 out -> GEMM2 in), linear [row][128]
__device__ __align__(16) __nv_bfloat16 g_hi[(size_t)NROWS_PAD * DIM];
__device__ __align__(16) __nv_bfloat16 g_lo[(size_t)NROWS_PAD * DIM];
// W^T images Bs[n][k] = W[k][n], 6 = layer*2 + {0:W1, 1:W2}
__device__ __align__(16) __nv_bfloat16 g_bs_hi[6 * DIM * DIM];
__device__ __align__(16) __nv_bfloat16 g_bs_lo[6 * DIM * DIM];

// CSR by destination
__device__ int g_cnt[NNODES];
__device__ int g_rowptr[NNODES + 1];
__device__ int g_cur[NNODES];
__device__ int g_srcbuf[NEDGES];
__device__ int g_csum[NCHUNK];
__device__ int g_coff[NCHUNK];

// ---------------- CSR construction -------------------------------------------
__global__ void k_zero_cnt() {
    int i = blockIdx.x * blockDim.x + threadIdx.x;
    int stride = gridDim.x * blockDim.x;
    for (int j = i; j < NNODES; j += stride) g_cnt[j] = 0;
    if (blockIdx.x == 0 && threadIdx.x < DIM) {
        g_sum[threadIdx.x] = 0.f;
        g_sumsq[threadIdx.x] = 0.f;
    }
}

__global__ void k_hist(const int* __restrict__ ei) {
    int i = blockIdx.x * blockDim.x + threadIdx.x;
    int stride = gridDim.x * blockDim.x;
    for (int e = i; e < NEDGES; e += stride)
        atomicAdd(&g_cnt[ei[NEDGES + e]], 1);
}

__global__ void k_chunksum() {
    __shared__ int wsum[32];
    int i = blockIdx.x * 1024 + threadIdx.x;
    int v = (i < NNODES) ? g_cnt[i] : 0;
    #pragma unroll
    for (int o = 16; o > 0; o >>= 1) v += __shfl_down_sync(~0u, v, o);
    if ((threadIdx.x & 31) == 0) wsum[threadIdx.x >> 5] = v;
    __syncthreads();
    if (threadIdx.x < 32) {
        int s = wsum[threadIdx.x];
        #pragma unroll
        for (int o = 16; o > 0; o >>= 1) s += __shfl_down_sync(~0u, s, o);
        if (threadIdx.x == 0) g_csum[blockIdx.x] = s;
    }
}

__global__ void k_scanchunks() {
    __shared__ int sh[4];
    const int tid = threadIdx.x;
    const int lane = tid & 31;
    const int wid = tid >> 5;
    int v = (tid < NCHUNK) ? g_csum[tid] : 0;
    int x = v;
    #pragma unroll
    for (int o = 1; o < 32; o <<= 1) {
        int t = __shfl_up_sync(~0u, x, o);
        if (lane >= o) x += t;
    }
    if (lane == 31) sh[wid] = x;
    __syncthreads();
    int base = 0;
    #pragma unroll
    for (int w = 0; w < 4; w++) if (w < wid) base += sh[w];
    int excl = base + x - v;
    if (tid < NCHUNK) g_coff[tid] = excl;
    if (tid == 127) g_rowptr[NNODES] = base + x;
}

__global__ void k_scanwrite() {
    __shared__ int wsum[32];
    const int tid = threadIdx.x;
    const int lane = tid & 31;
    const int wid = tid >> 5;
    int i = blockIdx.x * 1024 + tid;
    int v = (i < NNODES) ? g_cnt[i] : 0;
    int x = v;
    #pragma unroll
    for (int o = 1; o < 32; o <<= 1) {
        int t = __shfl_up_sync(~0u, x, o);
        if (lane >= o) x += t;
    }
    if (lane == 31) wsum[wid] = x;
    __syncthreads();
    if (wid == 0) {
        int s = wsum[lane];
        #pragma unroll
        for (int o = 1; o < 32; o <<= 1) {
            int t = __shfl_up_sync(~0u, s, o);
            if (lane >= o) s += t;
        }
        wsum[lane] = s;
    }
    __syncthreads();
    int excl = g_coff[blockIdx.x] + x - v + (wid > 0 ? wsum[wid - 1] : 0);
    if (i < NNODES) { g_rowptr[i] = excl; g_cur[i] = excl; }
}

__global__ void k_fill(const int* __restrict__ ei) {
    int i = blockIdx.x * blockDim.x + threadIdx.x;
    int stride = gridDim.x * blockDim.x;
    for (int e = i; e < NEDGES; e += stride) {
        int d = ei[NEDGES + e];
        int pos = atomicAdd(&g_cur[d], 1);
        g_srcbuf[pos] = ei[e];
    }
}

// ---------------- W^T -> bf16 hi/lo Bs[n][k] (once per call) ------------------
__global__ void k_wconv(const float* __restrict__ W1, const float* __restrict__ W2) {
    int which = blockIdx.x;                 // layer*2 + {0,1}
    int layer = which >> 1;
    const float* W = (which & 1) ? (W2 + (size_t)layer * DIM * DIM)
                                 : (W1 + (size_t)layer * DIM * DIM);
    __nv_bfloat16* hi = g_bs_hi + (size_t)which * DIM * DIM;
    __nv_bfloat16* lo = g_bs_lo + (size_t)which * DIM * DIM;
    for (int e = threadIdx.x; e < DIM * DIM; e += blockDim.x) {
        int n = e >> 7, k = e & 127;
        float x = W[k * DIM + n];           // Bs[n][k] = W[k][n]
        __nv_bfloat16 h = __float2bfloat16(x);
        __nv_bfloat16 l = __float2bfloat16(x - __bfloat162float(h));
        hi[e] = h;
        lo[e] = l;
    }
}

// ---------------- gather aggregation: aggr[n] = z[n] + sum_{j->n} z[j] --------
__global__ void k_aggregate(const float* __restrict__ zin, int pin) {
    const int lane = threadIdx.x & 31;
    const int w = (blockIdx.x * blockDim.x + threadIdx.x) >> 5;
    if (w >= NNODES) return;
    const int c = lane * 4;
    const int beg = g_rowptr[w];
    const int end = g_rowptr[w + 1];
    float4 a0 = *(const float4*)(zin + (size_t)w * pin + c);
    float4 a1 = make_float4(0.f, 0.f, 0.f, 0.f);
    float4 a2 = a1, a3 = a1;
    int e = beg;
    for (; e + 4 <= end; e += 4) {
        int s0 = g_srcbuf[e], s1 = g_srcbuf[e + 1];
        int s2 = g_srcbuf[e + 2], s3 = g_srcbuf[e + 3];
        float4 v0 = *(const float4*)(zin + (size_t)s0 * pin + c);
        float4 v1 = *(const float4*)(zin + (size_t)s1 * pin + c);
        float4 v2 = *(const float4*)(zin + (size_t)s2 * pin + c);
        float4 v3 = *(const float4*)(zin + (size_t)s3 * pin + c);
        a0.x += v0.x; a0.y += v0.y; a0.z += v0.z; a0.w += v0.w;
        a1.x += v1.x; a1.y += v1.y; a1.z += v1.z; a1.w += v1.w;
        a2.x += v2.x; a2.y += v2.y; a2.z += v2.z; a2.w += v2.w;
        a3.x += v3.x; a3.y += v3.y; a3.z += v3.z; a3.w += v3.w;
    }
    for (; e < end; e++) {
        int s = g_srcbuf[e];
        float4 v = *(const float4*)(zin + (size_t)s * pin + c);
        a0.x += v.x; a0.y += v.y; a0.z += v.z; a0.w += v.w;
    }
    a0.x += a1.x + a2.x + a3.x;
    a0.y += a1.y + a2.y + a3.y;
    a0.z += a1.z + a2.z + a3.z;
    a0.w += a1.w + a2.w + a3.w;
    *(float4*)(g_aggr + (size_t)w * DIM + c) = a0;
}

// ---------------- mma.sync bf16-split GEMM -------------------------------------
// D = A @ W + bias, relu. 3 passes: Ahi*Bhi + Ahi*Blo + Alo*Bhi (f32 accum).
// MODE 0 (GEMM1): A from fp32, out -> bf16 hi/lo linear buffers
// MODE 1 (GEMM2): A from bf16 hi/lo buffers, out -> fp32 h + fused BN stats
#define PITCH 136                      // bf16 units; 272B row stride: conflict-free
#define PITCHB 272
#define SM_AHI 0
#define SM_ALO (SM_AHI + 128 * PITCHB)
#define SM_BHI (SM_ALO + 128 * PITCHB)
#define SM_BLO (SM_BHI + 128 * PITCHB)
#define SM_SUM (SM_BLO + 128 * PITCHB)       // float [8][128]
#define SM_SQ  (SM_SUM + 8 * 128 * 4)
#define SMEM_TOT (SM_SQ + 8 * 128 * 4)

#define MMA16816(c, a0, a1, a2, a3, b0, b1) \
    asm volatile("mma.sync.aligned.m16n8k16.row.col.f32.bf16.bf16.f32 " \
        "{%0,%1,%2,%3}, {%4,%5,%6,%7}, {%8,%9}, {%0,%1,%2,%3};" \
        : "+f"((c)[0]), "+f"((c)[1]), "+f"((c)[2]), "+f"((c)[3]) \
        : "r"(a0), "r"(a1), "r"(a2), "r"(a3), "r"(b0), "r"(b1))

__device__ __forceinline__ uint32_t pack_hi2(float x0, float x1, uint32_t& lo) {
    __nv_bfloat16 h0 = __float2bfloat16(x0);
    __nv_bfloat16 h1 = __float2bfloat16(x1);
    __nv_bfloat16 l0 = __float2bfloat16(x0 - __bfloat162float(h0));
    __nv_bfloat16 l1 = __float2bfloat16(x1 - __bfloat162float(h1));
    lo = (uint32_t)__bfloat16_as_ushort(l0) | ((uint32_t)__bfloat16_as_ushort(l1) << 16);
    return (uint32_t)__bfloat16_as_ushort(h0) | ((uint32_t)__bfloat16_as_ushort(h1) << 16);
}

template <int MODE>
__global__ void __launch_bounds__(256, 1)
k_mma(const float* __restrict__ Afp,
      const __nv_bfloat16* __restrict__ Ahi,
      const __nv_bfloat16* __restrict__ Alo,
      const __nv_bfloat16* __restrict__ Bhi,
      const __nv_bfloat16* __restrict__ Blo,
      const float* __restrict__ bias,
      float* __restrict__ outh,
      __nv_bfloat16* __restrict__ Ohi,
      __nv_bfloat16* __restrict__ Olo,
      int nrows) {
    extern __shared__ char smem[];
    const int tid = threadIdx.x;
    const int wid = tid >> 5;
    const int lane = tid & 31;
    const int g = lane >> 2;           // group id (row within 8)
    const int t = lane & 3;            // thread in group (k/col pair)
    const int row0 = blockIdx.x * 128;

    // zero stats staging
    if (MODE == 1) {
        float* z = (float*)(smem + SM_SUM);
        #pragma unroll
        for (int i = 0; i < 8; i++) z[tid + i * 256] = 0.f;
    }

    // load B hi/lo: Bs[n][k] 16384 bf16 = 2048 uint4
    {
        const uint4* bh = (const uint4*)Bhi;
        const uint4* bl = (const uint4*)Blo;
        #pragma unroll
        for (int i = 0; i < 8; i++) {
            int idx = tid + i * 256;
            int r = idx >> 4, k = (idx & 15) * 8;
            *(uint4*)(smem + SM_BHI + r * PITCHB + k * 2) = bh[idx];
            *(uint4*)(smem + SM_BLO + r * PITCHB + k * 2) = bl[idx];
        }
    }

    // load A hi/lo
    if (MODE == 1) {
        const uint4* ah = (const uint4*)(Ahi + (size_t)row0 * DIM);
        const uint4* al = (const uint4*)(Alo + (size_t)row0 * DIM);
        #pragma unroll
        for (int i = 0; i < 8; i++) {
            int idx = tid + i * 256;
            int r = idx >> 4, k = (idx & 15) * 8;
            *(uint4*)(smem + SM_AHI + r * PITCHB + k * 2) = ah[idx];
            *(uint4*)(smem + SM_ALO + r * PITCHB + k * 2) = al[idx];
        }
    } else {
        #pragma unroll
        for (int i = 0; i < 16; i++) {
            int idx = tid + i * 256;           // over 4096 float4
            int r = idx >> 5, k = (idx & 31) * 4;
            int gr = row0 + r;
            float4 v = make_float4(0.f, 0.f, 0.f, 0.f);
            if (gr < nrows) v = *(const float4*)(Afp + (size_t)gr * DIM + k);
            uint32_t l0, l1, h0, h1;
            h0 = pack_hi2(v.x, v.y, l0);
            h1 = pack_hi2(v.z, v.w, l1);
            *(uint2*)(smem + SM_AHI + r * PITCHB + k * 2) = make_uint2(h0, h1);
            *(uint2*)(smem + SM_ALO + r * PITCHB + k * 2) = make_uint2(l0, l1);
        }
    }
    __syncthreads();

    // warp tile: 32m x 64n. wm = wid>>1, wn = wid&1
    const int m0 = (wid >> 1) * 32;
    const int n0 = (wid & 1) * 64;

    float c[2][8][4];
    #pragma unroll
    for (int mt = 0; mt < 2; mt++)
        #pragma unroll
        for (int nt = 0; nt < 8; nt++)
            #pragma unroll
            for (int q = 0; q < 4; q++) c[mt][nt][q] = 0.f;

    #pragma unroll
    for (int p = 0; p < 3; p++) {
        const char* As = smem + (p == 2 ? SM_ALO : SM_AHI);
        const char* Bs = smem + (p == 1 ? SM_BLO : SM_BHI);
        #pragma unroll
        for (int ks = 0; ks < 8; ks++) {
            const int kb = ks * 16;
            uint32_t a[2][4];
            #pragma unroll
            for (int mt = 0; mt < 2; mt++) {
                const char* pr = As + (m0 + mt * 16 + g) * PITCHB + (kb + 2 * t) * 2;
                a[mt][0] = *(const uint32_t*)pr;
                a[mt][1] = *(const uint32_t*)(pr + 8 * PITCHB);
                a[mt][2] = *(const uint32_t*)(pr + 16);
                a[mt][3] = *(const uint32_t*)(pr + 8 * PITCHB + 16);
            }
            #pragma unroll
            for (int nt = 0; nt < 8; nt++) {
                const char* pb = Bs + (n0 + nt * 8 + g) * PITCHB + (kb + 2 * t) * 2;
                uint32_t b0 = *(const uint32_t*)pb;
                uint32_t b1 = *(const uint32_t*)(pb + 16);
                MMA16816(c[0][nt], a[0][0], a[0][1], a[0][2], a[0][3], b0, b1);
                MMA16816(c[1][nt], a[1][0], a[1][1], a[1][2], a[1][3], b0, b1);
            }
        }
    }

    // epilogue. c[mt][nt]: {0,1} -> row m0+mt*16+g, cols n0+nt*8+2t{,+1};
    //                      {2,3} -> row +8
    #pragma unroll
    for (int nt = 0; nt < 8; nt++) {
        const int ce = n0 + nt * 8 + 2 * t;
        const float be = __ldg(bias + ce);
        const float bo = __ldg(bias + ce + 1);
        float se = 0.f, so = 0.f, qe = 0.f, qo = 0.f;
        #pragma unroll
        for (int mt = 0; mt < 2; mt++) {
            #pragma unroll
            for (int rr = 0; rr < 2; rr++) {
                const int gr = row0 + m0 + mt * 16 + g + rr * 8;
                float ve = fmaxf(c[mt][nt][rr * 2] + be, 0.f);
                float vo = fmaxf(c[mt][nt][rr * 2 + 1] + bo, 0.f);
                if (MODE == 0) {
                    uint32_t lo;
                    uint32_t hi = pack_hi2(ve, vo, lo);
                    *(uint32_t*)(Ohi + (size_t)gr * DIM + ce) = hi;
                    *(uint32_t*)(Olo + (size_t)gr * DIM + ce) = lo;
                } else {
                    if (gr >= nrows) { ve = 0.f; vo = 0.f; }
                    se += ve; so += vo;
                    qe += ve * ve; qo += vo * vo;
                    if (gr < nrows)
                        *(float2*)(outh + (size_t)gr * DIM + ce) = make_float2(ve, vo);
                }
            }
        }
        if (MODE == 1) {
            #pragma unroll
            for (int o = 4; o < 32; o <<= 1) {
                se += __shfl_xor_sync(~0u, se, o);
                so += __shfl_xor_sync(~0u, so, o);
                qe += __shfl_xor_sync(~0u, qe, o);
                qo += __shfl_xor_sync(~0u, qo, o);
            }
            if (g == 0) {
                float* ps = (float*)(smem + SM_SUM) + wid * 128;
                float* pq = (float*)(smem + SM_SQ) + wid * 128;
                ps[ce] = se; ps[ce + 1] = so;
                pq[ce] = qe; pq[ce + 1] = qo;
            }
        }
    }

    if (MODE == 1) {
        __syncthreads();
        if (tid < 128) {
            const float* ps = (const float*)(smem + SM_SUM);
            float s = 0.f;
            #pragma unroll
            for (int w = 0; w < 8; w++) s += ps[w * 128 + tid];
            atomicAdd(&g_sum[tid], s);
        } else {
            const float* pq = (const float*)(smem + SM_SQ);
            const int f = tid - 128;
            float s = 0.f;
            #pragma unroll
            for (int w = 0; w < 8; w++) s += pq[w * 128 + f];
            atomicAdd(&g_sumsq[f], s);
        }
    }
}

// ---------------- finalize BN (and zero stats for next layer) -----------------
__global__ void k_finalize(const float* __restrict__ gamma,
                           const float* __restrict__ beta) {
    int f = threadIdx.x;
    float mean = g_sum[f] * (1.0f / NNODES);
    float var = g_sumsq[f] * (1.0f / NNODES) - mean * mean;
    float inv = rsqrtf(var + BN_EPS);
    float sc = gamma[f] * inv;
    g_scale[f] = sc;
    g_shift[f] = beta[f] - mean * sc;
    g_sum[f] = 0.f;
    g_sumsq[f] = 0.f;
}

// ---------------- normalize + z_cat slice + graph add-pool --------------------
__global__ void k_zero_gcat(float* gcat) {
    int i = blockIdx.x * blockDim.x + threadIdx.x;
    if (i < NGRAPHS * NLAYERS * DIM) gcat[i] = 0.f;
}

#define NP_CH 512
__global__ void k_norm_pool(const float* __restrict__ h,
                            const int* __restrict__ batch,
                            float* __restrict__ zout,
                            float* __restrict__ gout) {
    const int f = threadIdx.x & 127;
    const int ln = threadIdx.x >> 7;
    const int r0 = blockIdx.x * NP_CH;
    const int rend = min(r0 + NP_CH, NNODES);
    const float sc = g_scale[f];
    const float sh = g_shift[f];
    float acc = 0.f;
    int cur = -1;
    for (int r = r0 + ln; r < rend; r += 4) {
        float v = fmaf(h[(size_t)r * DIM + f], sc, sh);
        zout[(size_t)r * (NLAYERS * DIM) + f] = v;
        int b = batch[r];
        if (b != cur) {
            if (cur >= 0) atomicAdd(&gout[(size_t)cur * (NLAYERS * DIM) + f], acc);
            cur = b;
            acc = v;
        } else {
            acc += v;
        }
    }
    if (cur >= 0) atomicAdd(&gout[(size_t)cur * (NLAYERS * DIM) + f], acc);
}

// ---------------- launch -------------------------------------------------------
extern "C" void kernel_launch(void* const* d_in, const int* in_sizes, int n_in,
                              void* d_out, int out_size) {
    const float* x     = (const float*)d_in[0];
    const int*   ei    = (const int*)d_in[1];
    const int*   batch = (const int*)d_in[2];
    const float* W1    = (const float*)d_in[3];
    const float* b1    = (const float*)d_in[4];
    const float* W2    = (const float*)d_in[5];
    const float* b2    = (const float*)d_in[6];
    const float* gamma = (const float*)d_in[7];
    const float* beta  = (const float*)d_in[8];

    float* z_cat = (float*)d_out;
    float* g_cat = z_cat + (size_t)NNODES * NLAYERS * DIM;

    cudaFuncSetAttribute(k_mma<0>, cudaFuncAttributeMaxDynamicSharedMemorySize, SMEM_TOT);
    cudaFuncSetAttribute(k_mma<1>, cudaFuncAttributeMaxDynamicSharedMemorySize, SMEM_TOT);

    float* aggr;  cudaGetSymbolAddress((void**)&aggr, g_aggr);
    float* hbuf;  cudaGetSymbolAddress((void**)&hbuf, g_h);
    __nv_bfloat16 *thi, *tlo, *bshi, *bslo;
    cudaGetSymbolAddress((void**)&thi, g_hi);
    cudaGetSymbolAddress((void**)&tlo, g_lo);
    cudaGetSymbolAddress((void**)&bshi, g_bs_hi);
    cudaGetSymbolAddress((void**)&bslo, g_bs_lo);

    // CSR build + W images
    k_zero_cnt<<<128, 512>>>();
    k_hist<<<1024, 512>>>(ei);
    k_chunksum<<<NCHUNK, 1024>>>();
    k_scanchunks<<<1, 128>>>();
    k_scanwrite<<<NCHUNK, 1024>>>();
    k_fill<<<1024, 512>>>(ei);
    k_wconv<<<6, 256>>>(W1, W2);

    k_zero_gcat<<<(NGRAPHS * NLAYERS * DIM + 255) / 256, 256>>>(g_cat);

    const int np_grid  = (NNODES + NP_CH - 1) / NP_CH;
    const int agg_grid = (NNODES * 32 + 255) / 256;

    for (int l = 0; l < NLAYERS; l++) {
        const float* zin = (l == 0) ? x : (z_cat + (size_t)(l - 1) * DIM);
        const int pin = (l == 0) ? DIM : (NLAYERS * DIM);

        k_aggregate<<<agg_grid, 256>>>(zin, pin);
        // GEMM1: hi/lo = split(relu(aggr @ W1 + b1))
        k_mma<0><<<NTILES, 256, SMEM_TOT>>>(
            aggr, nullptr, nullptr,
            bshi + (size_t)(l * 2) * DIM * DIM, bslo + (size_t)(l * 2) * DIM * DIM,
            b1 + (size_t)l * DIM, nullptr, thi, tlo, NNODES);
        // GEMM2: h = relu(hi/lo @ W2 + b2), fused BN stats
        k_mma<1><<<NTILES, 256, SMEM_TOT>>>(
            nullptr, thi, tlo,
            bshi + (size_t)(l * 2 + 1) * DIM * DIM, bslo + (size_t)(l * 2 + 1) * DIM * DIM,
            b2 + (size_t)l * DIM, hbuf, nullptr, nullptr, NNODES);
        k_finalize<<<1, 128>>>(gamma + (size_t)l * DIM, beta + (size_t)l * DIM);
        k_norm_pool<<<np_grid, 512>>>(hbuf, batch,
                                      z_cat + (size_t)l * DIM,
                                      g_cat + (size_t)l * DIM);
    }
}

// round 7
// speedup vs baseline: 1.5630x; 1.1796x over previous
#include <cuda_runtime.h>
#include <cuda_bf16.h>
#include <cstdint>

#define NNODES 100000
#define NEDGES 1600000
#define DIM 128
#define NGRAPHS 128
#define NLAYERS 3
#define BN_EPS 1e-5f
#define NCHUNK ((NNODES + 1023) / 1024)
#define NTILES ((NNODES + 127) / 128)

// ---------------- scratch (static device globals; no allocation) -------------
__device__ float g_aggr[(size_t)NNODES * DIM];   // aggregate out (MLP in, fp32)
__device__ float g_h[(size_t)NNODES * DIM];      // MLP out (pre-BN h, fp32)
__device__ float g_sum[DIM];
__device__ float g_sumsq[DIM];
__device__ float g_scale[DIM];
__device__ float g_shift[DIM];

// W^T images Bs[n][k] = W[k][n], 6 = layer*2 + {0:W1, 1:W2}
__device__ __align__(16) __nv_bfloat16 g_bs_hi[6 * DIM * DIM];
__device__ __align__(16) __nv_bfloat16 g_bs_lo[6 * DIM * DIM];

// CSR by destination
__device__ int g_cnt[NNODES];
__device__ int g_rowptr[NNODES + 1];
__device__ int g_cur[NNODES];
__device__ int g_srcbuf[NEDGES];
__device__ int g_csum[NCHUNK];
__device__ int g_coff[NCHUNK];

// ---------------- CSR construction -------------------------------------------
__global__ void k_zero_cnt() {
    int i = blockIdx.x * blockDim.x + threadIdx.x;
    int stride = gridDim.x * blockDim.x;
    for (int j = i; j < NNODES; j += stride) g_cnt[j] = 0;
    if (blockIdx.x == 0 && threadIdx.x < DIM) {
        g_sum[threadIdx.x] = 0.f;
        g_sumsq[threadIdx.x] = 0.f;
    }
}

__global__ void k_hist(const int* __restrict__ ei) {
    int i = blockIdx.x * blockDim.x + threadIdx.x;
    int stride = gridDim.x * blockDim.x;
    for (int e = i; e < NEDGES; e += stride)
        atomicAdd(&g_cnt[ei[NEDGES + e]], 1);
}

__global__ void k_chunksum() {
    __shared__ int wsum[32];
    int i = blockIdx.x * 1024 + threadIdx.x;
    int v = (i < NNODES) ? g_cnt[i] : 0;
    #pragma unroll
    for (int o = 16; o > 0; o >>= 1) v += __shfl_down_sync(~0u, v, o);
    if ((threadIdx.x & 31) == 0) wsum[threadIdx.x >> 5] = v;
    __syncthreads();
    if (threadIdx.x < 32) {
        int s = wsum[threadIdx.x];
        #pragma unroll
        for (int o = 16; o > 0; o >>= 1) s += __shfl_down_sync(~0u, s, o);
        if (threadIdx.x == 0) g_csum[blockIdx.x] = s;
    }
}

__global__ void k_scanchunks() {
    __shared__ int sh[4];
    const int tid = threadIdx.x;
    const int lane = tid & 31;
    const int wid = tid >> 5;
    int v = (tid < NCHUNK) ? g_csum[tid] : 0;
    int x = v;
    #pragma unroll
    for (int o = 1; o < 32; o <<= 1) {
        int t = __shfl_up_sync(~0u, x, o);
        if (lane >= o) x += t;
    }
    if (lane == 31) sh[wid] = x;
    __syncthreads();
    int base = 0;
    #pragma unroll
    for (int w = 0; w < 4; w++) if (w < wid) base += sh[w];
    int excl = base + x - v;
    if (tid < NCHUNK) g_coff[tid] = excl;
    if (tid == 127) g_rowptr[NNODES] = base + x;
}

__global__ void k_scanwrite() {
    __shared__ int wsum[32];
    const int tid = threadIdx.x;
    const int lane = tid & 31;
    const int wid = tid >> 5;
    int i = blockIdx.x * 1024 + tid;
    int v = (i < NNODES) ? g_cnt[i] : 0;
    int x = v;
    #pragma unroll
    for (int o = 1; o < 32; o <<= 1) {
        int t = __shfl_up_sync(~0u, x, o);
        if (lane >= o) x += t;
    }
    if (lane == 31) wsum[wid] = x;
    __syncthreads();
    if (wid == 0) {
        int s = wsum[lane];
        #pragma unroll
        for (int o = 1; o < 32; o <<= 1) {
            int t = __shfl_up_sync(~0u, s, o);
            if (lane >= o) s += t;
        }
        wsum[lane] = s;
    }
    __syncthreads();
    int excl = g_coff[blockIdx.x] + x - v + (wid > 0 ? wsum[wid - 1] : 0);
    if (i < NNODES) { g_rowptr[i] = excl; g_cur[i] = excl; }
}

__global__ void k_fill(const int* __restrict__ ei) {
    int i = blockIdx.x * blockDim.x + threadIdx.x;
    int stride = gridDim.x * blockDim.x;
    for (int e = i; e < NEDGES; e += stride) {
        int d = ei[NEDGES + e];
        int pos = atomicAdd(&g_cur[d], 1);
        g_srcbuf[pos] = ei[e];
    }
}

// ---------------- W^T -> bf16 hi/lo Bs[n][k] (once per call) ------------------
__global__ void k_wconv(const float* __restrict__ W1, const float* __restrict__ W2) {
    int which = blockIdx.x;                 // layer*2 + {0,1}
    int layer = which >> 1;
    const float* W = (which & 1) ? (W2 + (size_t)layer * DIM * DIM)
                                 : (W1 + (size_t)layer * DIM * DIM);
    __nv_bfloat16* hi = g_bs_hi + (size_t)which * DIM * DIM;
    __nv_bfloat16* lo = g_bs_lo + (size_t)which * DIM * DIM;
    for (int e = threadIdx.x; e < DIM * DIM; e += blockDim.x) {
        int n = e >> 7, k = e & 127;
        float x = W[k * DIM + n];           // Bs[n][k] = W[k][n]
        __nv_bfloat16 h = __float2bfloat16(x);
        __nv_bfloat16 l = __float2bfloat16(x - __bfloat162float(h));
        hi[e] = h;
        lo[e] = l;
    }
}

// ---------------- gather aggregation: aggr[n] = z[n] + sum_{j->n} z[j] --------
__global__ void k_aggregate(const float* __restrict__ zin, int pin) {
    const int lane = threadIdx.x & 31;
    const int w = (blockIdx.x * blockDim.x + threadIdx.x) >> 5;
    if (w >= NNODES) return;
    const int c = lane * 4;
    const int beg = g_rowptr[w];
    const int end = g_rowptr[w + 1];
    float4 a0 = *(const float4*)(zin + (size_t)w * pin + c);
    float4 a1 = make_float4(0.f, 0.f, 0.f, 0.f);
    float4 a2 = a1, a3 = a1;
    int e = beg;
    for (; e + 4 <= end; e += 4) {
        int s0 = g_srcbuf[e], s1 = g_srcbuf[e + 1];
        int s2 = g_srcbuf[e + 2], s3 = g_srcbuf[e + 3];
        float4 v0 = *(const float4*)(zin + (size_t)s0 * pin + c);
        float4 v1 = *(const float4*)(zin + (size_t)s1 * pin + c);
        float4 v2 = *(const float4*)(zin + (size_t)s2 * pin + c);
        float4 v3 = *(const float4*)(zin + (size_t)s3 * pin + c);
        a0.x += v0.x; a0.y += v0.y; a0.z += v0.z; a0.w += v0.w;
        a1.x += v1.x; a1.y += v1.y; a1.z += v1.z; a1.w += v1.w;
        a2.x += v2.x; a2.y += v2.y; a2.z += v2.z; a2.w += v2.w;
        a3.x += v3.x; a3.y += v3.y; a3.z += v3.z; a3.w += v3.w;
    }
    for (; e < end; e++) {
        int s = g_srcbuf[e];
        float4 v = *(const float4*)(zin + (size_t)s * pin + c);
        a0.x += v.x; a0.y += v.y; a0.z += v.z; a0.w += v.w;
    }
    a0.x += a1.x + a2.x + a3.x;
    a0.y += a1.y + a2.y + a3.y;
    a0.z += a1.z + a2.z + a3.z;
    a0.w += a1.w + a2.w + a3.w;
    *(float4*)(g_aggr + (size_t)w * DIM + c) = a0;
}

// ---------------- fused 2-GEMM MLP: h = relu(relu(A@W1+b1)@W2+b2) + BN stats --
// bf16-split mma.sync: 3 passes per GEMM (hi*hi + hi*lo + lo*hi), f32 accum.
#define PITCHB 272                     // 136 bf16 per row: conflict-free
#define SM_AHI 0
#define SM_ALO (SM_AHI + 128 * PITCHB)
#define SM_B1HI (SM_ALO + 128 * PITCHB)
#define SM_B1LO (SM_B1HI + 128 * PITCHB)
#define SM_B2HI (SM_B1LO + 128 * PITCHB)
#define SM_B2LO (SM_B2HI + 128 * PITCHB)
#define SM_SUM (SM_B2LO + 128 * PITCHB)       // float [8][128]
#define SM_SQ  (SM_SUM + 8 * 128 * 4)
#define SMEM_TOT (SM_SQ + 8 * 128 * 4)

#define MMA16816(c, a0, a1, a2, a3, b0, b1) \
    asm volatile("mma.sync.aligned.m16n8k16.row.col.f32.bf16.bf16.f32 " \
        "{%0,%1,%2,%3}, {%4,%5,%6,%7}, {%8,%9}, {%0,%1,%2,%3};" \
        : "+f"((c)[0]), "+f"((c)[1]), "+f"((c)[2]), "+f"((c)[3]) \
        : "r"(a0), "r"(a1), "r"(a2), "r"(a3), "r"(b0), "r"(b1))

__device__ __forceinline__ uint32_t pack_hi2(float x0, float x1, uint32_t& lo) {
    __nv_bfloat16 h0 = __float2bfloat16(x0);
    __nv_bfloat16 h1 = __float2bfloat16(x1);
    __nv_bfloat16 l0 = __float2bfloat16(x0 - __bfloat162float(h0));
    __nv_bfloat16 l1 = __float2bfloat16(x1 - __bfloat162float(h1));
    lo = (uint32_t)__bfloat16_as_ushort(l0) | ((uint32_t)__bfloat16_as_ushort(l1) << 16);
    return (uint32_t)__bfloat16_as_ushort(h0) | ((uint32_t)__bfloat16_as_ushort(h1) << 16);
}

// MMA over current A planes with B planes at (bhi_off, blo_off)
__device__ __forceinline__ void mma_3pass(char* smem, int bhi_off, int blo_off,
                                          int m0, int n0, int g, int t,
                                          float c[2][8][4]) {
    #pragma unroll
    for (int mt = 0; mt < 2; mt++)
        #pragma unroll
        for (int nt = 0; nt < 8; nt++)
            #pragma unroll
            for (int q = 0; q < 4; q++) c[mt][nt][q] = 0.f;
    #pragma unroll
    for (int p = 0; p < 3; p++) {
        const char* As = smem + (p == 2 ? SM_ALO : SM_AHI);
        const char* Bs = smem + (p == 1 ? blo_off : bhi_off);
        #pragma unroll
        for (int ks = 0; ks < 8; ks++) {
            const int kb = ks * 16;
            uint32_t a[2][4];
            #pragma unroll
            for (int mt = 0; mt < 2; mt++) {
                const char* pr = As + (m0 + mt * 16 + g) * PITCHB + (kb + 2 * t) * 2;
                a[mt][0] = *(const uint32_t*)pr;
                a[mt][1] = *(const uint32_t*)(pr + 8 * PITCHB);
                a[mt][2] = *(const uint32_t*)(pr + 16);
                a[mt][3] = *(const uint32_t*)(pr + 8 * PITCHB + 16);
            }
            #pragma unroll
            for (int nt = 0; nt < 8; nt++) {
                const char* pb = Bs + (n0 + nt * 8 + g) * PITCHB + (kb + 2 * t) * 2;
                uint32_t b0 = *(const uint32_t*)pb;
                uint32_t b1 = *(const uint32_t*)(pb + 16);
                MMA16816(c[0][nt], a[0][0], a[0][1], a[0][2], a[0][3], b0, b1);
                MMA16816(c[1][nt], a[1][0], a[1][1], a[1][2], a[1][3], b0, b1);
            }
        }
    }
}

__global__ void __launch_bounds__(256, 1)
k_mlp(const float* __restrict__ Afp,
      const __nv_bfloat16* __restrict__ B1hi, const __nv_bfloat16* __restrict__ B1lo,
      const __nv_bfloat16* __restrict__ B2hi, const __nv_bfloat16* __restrict__ B2lo,
      const float* __restrict__ bias1, const float* __restrict__ bias2,
      float* __restrict__ outh, int nrows) {
    extern __shared__ char smem[];
    const int tid = threadIdx.x;
    const int wid = tid >> 5;
    const int lane = tid & 31;
    const int g = lane >> 2;
    const int t = lane & 3;
    const int row0 = blockIdx.x * 128;

    // zero stats staging
    {
        float* z = (float*)(smem + SM_SUM);
        #pragma unroll
        for (int i = 0; i < 8; i++) z[tid + i * 256] = 0.f;
    }

    // load B1/B2 hi/lo: 4 x 2048 uint4
    {
        const uint4* s1h = (const uint4*)B1hi;
        const uint4* s1l = (const uint4*)B1lo;
        const uint4* s2h = (const uint4*)B2hi;
        const uint4* s2l = (const uint4*)B2lo;
        #pragma unroll
        for (int i = 0; i < 8; i++) {
            int idx = tid + i * 256;
            int r = idx >> 4, k = (idx & 15) * 8;
            int off = r * PITCHB + k * 2;
            *(uint4*)(smem + SM_B1HI + off) = s1h[idx];
            *(uint4*)(smem + SM_B1LO + off) = s1l[idx];
            *(uint4*)(smem + SM_B2HI + off) = s2h[idx];
            *(uint4*)(smem + SM_B2LO + off) = s2l[idx];
        }
    }

    // load + split A (fp32 -> bf16 hi/lo planes)
    {
        #pragma unroll
        for (int i = 0; i < 16; i++) {
            int idx = tid + i * 256;
            int r = idx >> 5, k = (idx & 31) * 4;
            int gr = row0 + r;
            float4 v = make_float4(0.f, 0.f, 0.f, 0.f);
            if (gr < nrows) v = *(const float4*)(Afp + (size_t)gr * DIM + k);
            uint32_t l0, l1, h0, h1;
            h0 = pack_hi2(v.x, v.y, l0);
            h1 = pack_hi2(v.z, v.w, l1);
            *(uint2*)(smem + SM_AHI + r * PITCHB + k * 2) = make_uint2(h0, h1);
            *(uint2*)(smem + SM_ALO + r * PITCHB + k * 2) = make_uint2(l0, l1);
        }
    }
    __syncthreads();

    const int m0 = (wid >> 1) * 32;
    const int n0 = (wid & 1) * 64;
    float c[2][8][4];

    // ---- GEMM1 ----
    mma_3pass(smem, SM_B1HI, SM_B1LO, m0, n0, g, t, c);
    __syncthreads();   // everyone done reading A planes

    // epilogue1: bias1+relu -> hi/lo back into A planes
    #pragma unroll
    for (int nt = 0; nt < 8; nt++) {
        const int ce = n0 + nt * 8 + 2 * t;
        const float be = __ldg(bias1 + ce);
        const float bo = __ldg(bias1 + ce + 1);
        #pragma unroll
        for (int mt = 0; mt < 2; mt++) {
            #pragma unroll
            for (int rr = 0; rr < 2; rr++) {
                const int r = m0 + mt * 16 + g + rr * 8;
                float ve = fmaxf(c[mt][nt][rr * 2] + be, 0.f);
                float vo = fmaxf(c[mt][nt][rr * 2 + 1] + bo, 0.f);
                uint32_t lo;
                uint32_t hi = pack_hi2(ve, vo, lo);
                *(uint32_t*)(smem + SM_AHI + r * PITCHB + ce * 2) = hi;
                *(uint32_t*)(smem + SM_ALO + r * PITCHB + ce * 2) = lo;
            }
        }
    }
    __syncthreads();

    // ---- GEMM2 ----
    mma_3pass(smem, SM_B2HI, SM_B2LO, m0, n0, g, t, c);

    // epilogue2: bias2+relu -> fp32 out + stats
    #pragma unroll
    for (int nt = 0; nt < 8; nt++) {
        const int ce = n0 + nt * 8 + 2 * t;
        const float be = __ldg(bias2 + ce);
        const float bo = __ldg(bias2 + ce + 1);
        float se = 0.f, so = 0.f, qe = 0.f, qo = 0.f;
        #pragma unroll
        for (int mt = 0; mt < 2; mt++) {
            #pragma unroll
            for (int rr = 0; rr < 2; rr++) {
                const int gr = row0 + m0 + mt * 16 + g + rr * 8;
                float ve = fmaxf(c[mt][nt][rr * 2] + be, 0.f);
                float vo = fmaxf(c[mt][nt][rr * 2 + 1] + bo, 0.f);
                if (gr >= nrows) { ve = 0.f; vo = 0.f; }
                se += ve; so += vo;
                qe += ve * ve; qo += vo * vo;
                if (gr < nrows)
                    *(float2*)(outh + (size_t)gr * DIM + ce) = make_float2(ve, vo);
            }
        }
        #pragma unroll
        for (int o = 4; o < 32; o <<= 1) {
            se += __shfl_xor_sync(~0u, se, o);
            so += __shfl_xor_sync(~0u, so, o);
            qe += __shfl_xor_sync(~0u, qe, o);
            qo += __shfl_xor_sync(~0u, qo, o);
        }
        if (g == 0) {
            float* ps = (float*)(smem + SM_SUM) + wid * 128;
            float* pq = (float*)(smem + SM_SQ) + wid * 128;
            ps[ce] = se; ps[ce + 1] = so;
            pq[ce] = qe; pq[ce + 1] = qo;
        }
    }

    __syncthreads();
    if (tid < 128) {
        const float* ps = (const float*)(smem + SM_SUM);
        float s = 0.f;
        #pragma unroll
        for (int w = 0; w < 8; w++) s += ps[w * 128 + tid];
        atomicAdd(&g_sum[tid], s);
    } else {
        const float* pq = (const float*)(smem + SM_SQ);
        const int f = tid - 128;
        float s = 0.f;
        #pragma unroll
        for (int w = 0; w < 8; w++) s += pq[w * 128 + f];
        atomicAdd(&g_sumsq[f], s);
    }
}

// ---------------- finalize BN (and zero stats for next layer) -----------------
__global__ void k_finalize(const float* __restrict__ gamma,
                           const float* __restrict__ beta) {
    int f = threadIdx.x;
    float mean = g_sum[f] * (1.0f / NNODES);
    float var = g_sumsq[f] * (1.0f / NNODES) - mean * mean;
    float inv = rsqrtf(var + BN_EPS);
    float sc = gamma[f] * inv;
    g_scale[f] = sc;
    g_shift[f] = beta[f] - mean * sc;
    g_sum[f] = 0.f;
    g_sumsq[f] = 0.f;
}

// ---------------- normalize + z_cat slice + graph add-pool (float4) -----------
__global__ void k_zero_gcat(float* gcat) {
    int i = blockIdx.x * blockDim.x + threadIdx.x;
    if (i < NGRAPHS * NLAYERS * DIM) gcat[i] = 0.f;
}

#define NP_CH 512
__global__ void k_norm_pool(const float* __restrict__ h,
                            const int* __restrict__ batch,
                            float* __restrict__ zout,
                            float* __restrict__ gout) {
    const int f4 = (threadIdx.x & 31) * 4;   // feature group of 4
    const int ln = threadIdx.x >> 5;         // 0..7 row lane
    const int r0 = blockIdx.x * NP_CH;
    const int rend = min(r0 + NP_CH, NNODES);
    const float4 sc = *(const float4*)(g_scale + f4);
    const float4 sh = *(const float4*)(g_shift + f4);
    float4 acc = make_float4(0.f, 0.f, 0.f, 0.f);
    int cur = -1;
    for (int r = r0 + ln; r < rend; r += 8) {
        float4 x = *(const float4*)(h + (size_t)r * DIM + f4);
        float4 v;
        v.x = fmaf(x.x, sc.x, sh.x);
        v.y = fmaf(x.y, sc.y, sh.y);
        v.z = fmaf(x.z, sc.z, sh.z);
        v.w = fmaf(x.w, sc.w, sh.w);
        *(float4*)(zout + (size_t)r * (NLAYERS * DIM) + f4) = v;
        int b = batch[r];
        if (b != cur) {
            if (cur >= 0) {
                float* p = gout + (size_t)cur * (NLAYERS * DIM) + f4;
                atomicAdd(p, acc.x); atomicAdd(p + 1, acc.y);
                atomicAdd(p + 2, acc.z); atomicAdd(p + 3, acc.w);
            }
            cur = b;
            acc = v;
        } else {
            acc.x += v.x; acc.y += v.y; acc.z += v.z; acc.w += v.w;
        }
    }
    if (cur >= 0) {
        float* p = gout + (size_t)cur * (NLAYERS * DIM) + f4;
        atomicAdd(p, acc.x); atomicAdd(p + 1, acc.y);
        atomicAdd(p + 2, acc.z); atomicAdd(p + 3, acc.w);
    }
}

// ---------------- launch -------------------------------------------------------
extern "C" void kernel_launch(void* const* d_in, const int* in_sizes, int n_in,
                              void* d_out, int out_size) {
    const float* x     = (const float*)d_in[0];
    const int*   ei    = (const int*)d_in[1];
    const int*   batch = (const int*)d_in[2];
    const float* W1    = (const float*)d_in[3];
    const float* b1    = (const float*)d_in[4];
    const float* W2    = (const float*)d_in[5];
    const float* b2    = (const float*)d_in[6];
    const float* gamma = (const float*)d_in[7];
    const float* beta  = (const float*)d_in[8];

    float* z_cat = (float*)d_out;
    float* g_cat = z_cat + (size_t)NNODES * NLAYERS * DIM;

    cudaFuncSetAttribute(k_mlp, cudaFuncAttributeMaxDynamicSharedMemorySize, SMEM_TOT);

    float* aggr;  cudaGetSymbolAddress((void**)&aggr, g_aggr);
    float* hbuf;  cudaGetSymbolAddress((void**)&hbuf, g_h);
    __nv_bfloat16 *bshi, *bslo;
    cudaGetSymbolAddress((void**)&bshi, g_bs_hi);
    cudaGetSymbolAddress((void**)&bslo, g_bs_lo);

    // CSR build + W images
    k_zero_cnt<<<128, 512>>>();
    k_hist<<<1024, 512>>>(ei);
    k_chunksum<<<NCHUNK, 1024>>>();
    k_scanchunks<<<1, 128>>>();
    k_scanwrite<<<NCHUNK, 1024>>>();
    k_fill<<<1024, 512>>>(ei);
    k_wconv<<<6, 256>>>(W1, W2);

    k_zero_gcat<<<(NGRAPHS * NLAYERS * DIM + 255) / 256, 256>>>(g_cat);

    const int np_grid  = (NNODES + NP_CH - 1) / NP_CH;
    const int agg_grid = (NNODES * 32 + 255) / 256;

    for (int l = 0; l < NLAYERS; l++) {
        const float* zin = (l == 0) ? x : (z_cat + (size_t)(l - 1) * DIM);
        const int pin = (l == 0) ? DIM : (NLAYERS * DIM);

        k_aggregate<<<agg_grid, 256>>>(zin, pin);
        k_mlp<<<NTILES, 256, SMEM_TOT>>>(
            aggr,
            bshi + (size_t)(l * 2) * DIM * DIM, bslo + (size_t)(l * 2) * DIM * DIM,
            bshi + (size_t)(l * 2 + 1) * DIM * DIM, bslo + (size_t)(l * 2 + 1) * DIM * DIM,
            b1 + (size_t)l * DIM, b2 + (size_t)l * DIM, hbuf, NNODES);
        k_finalize<<<1, 128>>>(gamma + (size_t)l * DIM, beta + (size_t)l * DIM);
        k_norm_pool<<<np_grid, 256>>>(hbuf, batch,
                                      z_cat + (size_t)l * DIM,
                                      g_cat + (size_t)l * DIM);
    }
}

// round 8
// speedup vs baseline: 1.5918x; 1.0184x over previous
#include <cuda_runtime.h>
#include <cuda_bf16.h>
#include <cstdint>

#define NNODES 100000
#define NEDGES 1600000
#define DIM 128
#define NGRAPHS 128
#define NLAYERS 3
#define BN_EPS 1e-5f
#define NCHUNK ((NNODES + 1023) / 1024)
#define NTILES ((NNODES + 127) / 128)
#define NSMS 148

// ---------------- scratch (static device globals; no allocation) -------------
__device__ float g_aggr[(size_t)NNODES * DIM];   // aggregate out (MLP in, fp32)
__device__ float g_h[(size_t)NNODES * DIM];      // MLP out (pre-BN h, fp32)
__device__ float g_sum[DIM];
__device__ float g_sumsq[DIM];

// W^T images Bs[n][k] = W[k][n], 6 = layer*2 + {0:W1, 1:W2}
__device__ __align__(16) __nv_bfloat16 g_bs_hi[6 * DIM * DIM];
__device__ __align__(16) __nv_bfloat16 g_bs_lo[6 * DIM * DIM];

// CSR by destination
__device__ int g_cnt[NNODES];
__device__ int g_rowptr[NNODES + 1];
__device__ int g_cur[NNODES];
__device__ int g_srcbuf[NEDGES];
__device__ int g_csum[NCHUNK];
__device__ int g_coff[NCHUNK];

// ---------------- CSR construction -------------------------------------------
__global__ void k_zero_cnt(float* __restrict__ gcat) {
    int i = blockIdx.x * blockDim.x + threadIdx.x;
    int stride = gridDim.x * blockDim.x;
    for (int j = i; j < NNODES; j += stride) g_cnt[j] = 0;
    for (int j = i; j < NGRAPHS * NLAYERS * DIM; j += stride) gcat[j] = 0.f;
    if (blockIdx.x == 0 && threadIdx.x < DIM) {
        g_sum[threadIdx.x] = 0.f;
        g_sumsq[threadIdx.x] = 0.f;
    }
}

__global__ void k_hist(const int* __restrict__ ei) {
    int i = blockIdx.x * blockDim.x + threadIdx.x;
    if (i < NEDGES / 4) {
        int4 d = ((const int4*)(ei + NEDGES))[i];
        atomicAdd(&g_cnt[d.x], 1);
        atomicAdd(&g_cnt[d.y], 1);
        atomicAdd(&g_cnt[d.z], 1);
        atomicAdd(&g_cnt[d.w], 1);
    }
}

__global__ void k_chunksum() {
    __shared__ int wsum[32];
    int i = blockIdx.x * 1024 + threadIdx.x;
    int v = (i < NNODES) ? g_cnt[i] : 0;
    #pragma unroll
    for (int o = 16; o > 0; o >>= 1) v += __shfl_down_sync(~0u, v, o);
    if ((threadIdx.x & 31) == 0) wsum[threadIdx.x >> 5] = v;
    __syncthreads();
    if (threadIdx.x < 32) {
        int s = wsum[threadIdx.x];
        #pragma unroll
        for (int o = 16; o > 0; o >>= 1) s += __shfl_down_sync(~0u, s, o);
        if (threadIdx.x == 0) g_csum[blockIdx.x] = s;
    }
}

__global__ void k_scanchunks() {
    __shared__ int sh[4];
    const int tid = threadIdx.x;
    const int lane = tid & 31;
    const int wid = tid >> 5;
    int v = (tid < NCHUNK) ? g_csum[tid] : 0;
    int x = v;
    #pragma unroll
    for (int o = 1; o < 32; o <<= 1) {
        int t = __shfl_up_sync(~0u, x, o);
        if (lane >= o) x += t;
    }
    if (lane == 31) sh[wid] = x;
    __syncthreads();
    int base = 0;
    #pragma unroll
    for (int w = 0; w < 4; w++) if (w < wid) base += sh[w];
    int excl = base + x - v;
    if (tid < NCHUNK) g_coff[tid] = excl;
    if (tid == 127) g_rowptr[NNODES] = base + x;
}

__global__ void k_scanwrite() {
    __shared__ int wsum[32];
    const int tid = threadIdx.x;
    const int lane = tid & 31;
    const int wid = tid >> 5;
    int i = blockIdx.x * 1024 + tid;
    int v = (i < NNODES) ? g_cnt[i] : 0;
    int x = v;
    #pragma unroll
    for (int o = 1; o < 32; o <<= 1) {
        int t = __shfl_up_sync(~0u, x, o);
        if (lane >= o) x += t;
    }
    if (lane == 31) wsum[wid] = x;
    __syncthreads();
    if (wid == 0) {
        int s = wsum[lane];
        #pragma unroll
        for (int o = 1; o < 32; o <<= 1) {
            int t = __shfl_up_sync(~0u, s, o);
            if (lane >= o) s += t;
        }
        wsum[lane] = s;
    }
    __syncthreads();
    int excl = g_coff[blockIdx.x] + x - v + (wid > 0 ? wsum[wid - 1] : 0);
    if (i < NNODES) { g_rowptr[i] = excl; g_cur[i] = excl; }
}

__global__ void k_fill(const int* __restrict__ ei) {
    int i = blockIdx.x * blockDim.x + threadIdx.x;
    if (i < NEDGES / 4) {
        int4 s = ((const int4*)ei)[i];
        int4 d = ((const int4*)(ei + NEDGES))[i];
        int p0 = atomicAdd(&g_cur[d.x], 1); g_srcbuf[p0] = s.x;
        int p1 = atomicAdd(&g_cur[d.y], 1); g_srcbuf[p1] = s.y;
        int p2 = atomicAdd(&g_cur[d.z], 1); g_srcbuf[p2] = s.z;
        int p3 = atomicAdd(&g_cur[d.w], 1); g_srcbuf[p3] = s.w;
    }
}

// ---------------- W^T -> bf16 hi/lo Bs[n][k] (once per call) ------------------
__global__ void k_wconv(const float* __restrict__ W1, const float* __restrict__ W2) {
    int which = blockIdx.x;                 // layer*2 + {0,1}
    int layer = which >> 1;
    const float* W = (which & 1) ? (W2 + (size_t)layer * DIM * DIM)
                                 : (W1 + (size_t)layer * DIM * DIM);
    __nv_bfloat16* hi = g_bs_hi + (size_t)which * DIM * DIM;
    __nv_bfloat16* lo = g_bs_lo + (size_t)which * DIM * DIM;
    for (int e = threadIdx.x; e < DIM * DIM; e += blockDim.x) {
        int n = e >> 7, k = e & 127;
        float x = W[k * DIM + n];           // Bs[n][k] = W[k][n]
        __nv_bfloat16 h = __float2bfloat16(x);
        __nv_bfloat16 l = __float2bfloat16(x - __bfloat162float(h));
        hi[e] = h;
        lo[e] = l;
    }
}

// ---------------- gather aggregation: aggr[n] = z[n] + sum_{j->n} z[j] --------
// also zeroes BN stats for the upcoming layer (previous consumer already done)
__global__ void k_aggregate(const float* __restrict__ zin, int pin) {
    if (blockIdx.x == 0 && threadIdx.x < DIM) {
        g_sum[threadIdx.x] = 0.f;
        g_sumsq[threadIdx.x] = 0.f;
    }
    const int lane = threadIdx.x & 31;
    const int w = (blockIdx.x * blockDim.x + threadIdx.x) >> 5;
    if (w >= NNODES) return;
    const int c = lane * 4;
    const int beg = g_rowptr[w];
    const int end = g_rowptr[w + 1];
    float4 a0 = *(const float4*)(zin + (size_t)w * pin + c);
    float4 a1 = make_float4(0.f, 0.f, 0.f, 0.f);
    float4 a2 = a1, a3 = a1;
    int e = beg;
    for (; e + 4 <= end; e += 4) {
        int s0 = __ldg(g_srcbuf + e), s1 = __ldg(g_srcbuf + e + 1);
        int s2 = __ldg(g_srcbuf + e + 2), s3 = __ldg(g_srcbuf + e + 3);
        float4 v0 = *(const float4*)(zin + (size_t)s0 * pin + c);
        float4 v1 = *(const float4*)(zin + (size_t)s1 * pin + c);
        float4 v2 = *(const float4*)(zin + (size_t)s2 * pin + c);
        float4 v3 = *(const float4*)(zin + (size_t)s3 * pin + c);
        a0.x += v0.x; a0.y += v0.y; a0.z += v0.z; a0.w += v0.w;
        a1.x += v1.x; a1.y += v1.y; a1.z += v1.z; a1.w += v1.w;
        a2.x += v2.x; a2.y += v2.y; a2.z += v2.z; a2.w += v2.w;
        a3.x += v3.x; a3.y += v3.y; a3.z += v3.z; a3.w += v3.w;
    }
    for (; e < end; e++) {
        int s = __ldg(g_srcbuf + e);
        float4 v = *(const float4*)(zin + (size_t)s * pin + c);
        a0.x += v.x; a0.y += v.y; a0.z += v.z; a0.w += v.w;
    }
    a0.x += a1.x + a2.x + a3.x;
    a0.y += a1.y + a2.y + a3.y;
    a0.z += a1.z + a2.z + a3.z;
    a0.w += a1.w + a2.w + a3.w;
    *(float4*)(g_aggr + (size_t)w * DIM + c) = a0;
}

// ---------------- persistent fused 2-GEMM MLP + BN stats -----------------------
#define PITCHB 272
#define SM_AHI 0
#define SM_ALO (SM_AHI + 128 * PITCHB)
#define SM_B1HI (SM_ALO + 128 * PITCHB)
#define SM_B1LO (SM_B1HI + 128 * PITCHB)
#define SM_B2HI (SM_B1LO + 128 * PITCHB)
#define SM_B2LO (SM_B2HI + 128 * PITCHB)
#define SM_SUM (SM_B2LO + 128 * PITCHB)       // float [8][128]
#define SM_SQ  (SM_SUM + 8 * 128 * 4)
#define SM_BS1 (SM_SQ + 8 * 128 * 4)          // bias1 [128]
#define SM_BS2 (SM_BS1 + 512)                 // bias2 [128]
#define SMEM_TOT (SM_BS2 + 512)

#define MMA16816(c, a0, a1, a2, a3, b0, b1) \
    asm volatile("mma.sync.aligned.m16n8k16.row.col.f32.bf16.bf16.f32 " \
        "{%0,%1,%2,%3}, {%4,%5,%6,%7}, {%8,%9}, {%0,%1,%2,%3};" \
        : "+f"((c)[0]), "+f"((c)[1]), "+f"((c)[2]), "+f"((c)[3]) \
        : "r"(a0), "r"(a1), "r"(a2), "r"(a3), "r"(b0), "r"(b1))

__device__ __forceinline__ uint32_t pack_hi2(float x0, float x1, uint32_t& lo) {
    __nv_bfloat16 h0 = __float2bfloat16(x0);
    __nv_bfloat16 h1 = __float2bfloat16(x1);
    __nv_bfloat16 l0 = __float2bfloat16(x0 - __bfloat162float(h0));
    __nv_bfloat16 l1 = __float2bfloat16(x1 - __bfloat162float(h1));
    lo = (uint32_t)__bfloat16_as_ushort(l0) | ((uint32_t)__bfloat16_as_ushort(l1) << 16);
    return (uint32_t)__bfloat16_as_ushort(h0) | ((uint32_t)__bfloat16_as_ushort(h1) << 16);
}

__device__ __forceinline__ void mma_3pass(char* smem, int bhi_off, int blo_off,
                                          int m0, int n0, int g, int t,
                                          float c[2][8][4]) {
    #pragma unroll
    for (int mt = 0; mt < 2; mt++)
        #pragma unroll
        for (int nt = 0; nt < 8; nt++)
            #pragma unroll
            for (int q = 0; q < 4; q++) c[mt][nt][q] = 0.f;
    #pragma unroll
    for (int p = 0; p < 3; p++) {
        const char* As = smem + (p == 2 ? SM_ALO : SM_AHI);
        const char* Bs = smem + (p == 1 ? blo_off : bhi_off);
        #pragma unroll
        for (int ks = 0; ks < 8; ks++) {
            const int kb = ks * 16;
            uint32_t a[2][4];
            #pragma unroll
            for (int mt = 0; mt < 2; mt++) {
                const char* pr = As + (m0 + mt * 16 + g) * PITCHB + (kb + 2 * t) * 2;
                a[mt][0] = *(const uint32_t*)pr;
                a[mt][1] = *(const uint32_t*)(pr + 8 * PITCHB);
                a[mt][2] = *(const uint32_t*)(pr + 16);
                a[mt][3] = *(const uint32_t*)(pr + 8 * PITCHB + 16);
            }
            #pragma unroll
            for (int nt = 0; nt < 8; nt++) {
                const char* pb = Bs + (n0 + nt * 8 + g) * PITCHB + (kb + 2 * t) * 2;
                uint32_t b0 = *(const uint32_t*)pb;
                uint32_t b1 = *(const uint32_t*)(pb + 16);
                MMA16816(c[0][nt], a[0][0], a[0][1], a[0][2], a[0][3], b0, b1);
                MMA16816(c[1][nt], a[1][0], a[1][1], a[1][2], a[1][3], b0, b1);
            }
        }
    }
}

__global__ void __launch_bounds__(256, 1)
k_mlp(const float* __restrict__ Afp,
      const __nv_bfloat16* __restrict__ B1hi, const __nv_bfloat16* __restrict__ B1lo,
      const __nv_bfloat16* __restrict__ B2hi, const __nv_bfloat16* __restrict__ B2lo,
      const float* __restrict__ bias1, const float* __restrict__ bias2,
      float* __restrict__ outh, int nrows) {
    extern __shared__ char smem[];
    const int tid = threadIdx.x;
    const int wid = tid >> 5;
    const int lane = tid & 31;
    const int g = lane >> 2;
    const int t = lane & 3;

    // one-time setup: zero stats staging, load biases + B planes
    {
        float* z = (float*)(smem + SM_SUM);
        #pragma unroll
        for (int i = 0; i < 8; i++) z[tid + i * 256] = 0.f;
        if (tid < DIM) {
            ((float*)(smem + SM_BS1))[tid] = bias1[tid];
            ((float*)(smem + SM_BS2))[tid] = bias2[tid];
        }
        const uint4* s1h = (const uint4*)B1hi;
        const uint4* s1l = (const uint4*)B1lo;
        const uint4* s2h = (const uint4*)B2hi;
        const uint4* s2l = (const uint4*)B2lo;
        #pragma unroll
        for (int i = 0; i < 8; i++) {
            int idx = tid + i * 256;
            int r = idx >> 4, k = (idx & 15) * 8;
            int off = r * PITCHB + k * 2;
            *(uint4*)(smem + SM_B1HI + off) = s1h[idx];
            *(uint4*)(smem + SM_B1LO + off) = s1l[idx];
            *(uint4*)(smem + SM_B2HI + off) = s2h[idx];
            *(uint4*)(smem + SM_B2LO + off) = s2l[idx];
        }
    }

    const int m0 = (wid >> 1) * 32;
    const int n0 = (wid & 1) * 64;
    float c[2][8][4];

    for (int tile = blockIdx.x; tile < NTILES; tile += gridDim.x) {
        const int row0 = tile * 128;

        // load + split A (fp32 -> bf16 hi/lo planes)
        #pragma unroll
        for (int i = 0; i < 16; i++) {
            int idx = tid + i * 256;
            int r = idx >> 5, k = (idx & 31) * 4;
            int gr = row0 + r;
            float4 v = make_float4(0.f, 0.f, 0.f, 0.f);
            if (gr < nrows) v = *(const float4*)(Afp + (size_t)gr * DIM + k);
            uint32_t l0, l1, h0, h1;
            h0 = pack_hi2(v.x, v.y, l0);
            h1 = pack_hi2(v.z, v.w, l1);
            *(uint2*)(smem + SM_AHI + r * PITCHB + k * 2) = make_uint2(h0, h1);
            *(uint2*)(smem + SM_ALO + r * PITCHB + k * 2) = make_uint2(l0, l1);
        }
        __syncthreads();

        // ---- GEMM1 ----
        mma_3pass(smem, SM_B1HI, SM_B1LO, m0, n0, g, t, c);
        __syncthreads();

        // epilogue1: bias1+relu -> hi/lo back into A planes
        #pragma unroll
        for (int nt = 0; nt < 8; nt++) {
            const int ce = n0 + nt * 8 + 2 * t;
            const float be = ((const float*)(smem + SM_BS1))[ce];
            const float bo = ((const float*)(smem + SM_BS1))[ce + 1];
            #pragma unroll
            for (int mt = 0; mt < 2; mt++) {
                #pragma unroll
                for (int rr = 0; rr < 2; rr++) {
                    const int r = m0 + mt * 16 + g + rr * 8;
                    float ve = fmaxf(c[mt][nt][rr * 2] + be, 0.f);
                    float vo = fmaxf(c[mt][nt][rr * 2 + 1] + bo, 0.f);
                    uint32_t lo;
                    uint32_t hi = pack_hi2(ve, vo, lo);
                    *(uint32_t*)(smem + SM_AHI + r * PITCHB + ce * 2) = hi;
                    *(uint32_t*)(smem + SM_ALO + r * PITCHB + ce * 2) = lo;
                }
            }
        }
        __syncthreads();

        // ---- GEMM2 ----
        mma_3pass(smem, SM_B2HI, SM_B2LO, m0, n0, g, t, c);

        // epilogue2: bias2+relu -> fp32 out + stats
        #pragma unroll
        for (int nt = 0; nt < 8; nt++) {
            const int ce = n0 + nt * 8 + 2 * t;
            const float be = ((const float*)(smem + SM_BS2))[ce];
            const float bo = ((const float*)(smem + SM_BS2))[ce + 1];
            float se = 0.f, so = 0.f, qe = 0.f, qo = 0.f;
            #pragma unroll
            for (int mt = 0; mt < 2; mt++) {
                #pragma unroll
                for (int rr = 0; rr < 2; rr++) {
                    const int gr = row0 + m0 + mt * 16 + g + rr * 8;
                    float ve = fmaxf(c[mt][nt][rr * 2] + be, 0.f);
                    float vo = fmaxf(c[mt][nt][rr * 2 + 1] + bo, 0.f);
                    if (gr >= nrows) { ve = 0.f; vo = 0.f; }
                    se += ve; so += vo;
                    qe += ve * ve; qo += vo * vo;
                    if (gr < nrows)
                        *(float2*)(outh + (size_t)gr * DIM + ce) = make_float2(ve, vo);
                }
            }
            #pragma unroll
            for (int o = 4; o < 32; o <<= 1) {
                se += __shfl_xor_sync(~0u, se, o);
                so += __shfl_xor_sync(~0u, so, o);
                qe += __shfl_xor_sync(~0u, qe, o);
                qo += __shfl_xor_sync(~0u, qo, o);
            }
            if (g == 0) {
                float* ps = (float*)(smem + SM_SUM) + wid * 128;
                float* pq = (float*)(smem + SM_SQ) + wid * 128;
                ps[ce] = se; ps[ce + 1] = so;
                pq[ce] = qe; pq[ce + 1] = qo;
            }
        }
        __syncthreads();

        if (tid < 128) {
            const float* ps = (const float*)(smem + SM_SUM);
            float s = 0.f;
            #pragma unroll
            for (int w = 0; w < 8; w++) s += ps[w * 128 + tid];
            atomicAdd(&g_sum[tid], s);
        } else {
            const float* pq = (const float*)(smem + SM_SQ);
            const int f = tid - 128;
            float s = 0.f;
            #pragma unroll
            for (int w = 0; w < 8; w++) s += pq[w * 128 + f];
            atomicAdd(&g_sumsq[f], s);
        }
        __syncthreads();
    }
}

// ---------------- normalize + z_cat slice + graph add-pool (float4) -----------
// computes BN scale/shift per block from raw sums (k_finalize eliminated)
#define NP_CH 512
__global__ void k_norm_pool(const float* __restrict__ h,
                            const int* __restrict__ batch,
                            const float* __restrict__ gamma,
                            const float* __restrict__ beta,
                            float* __restrict__ zout,
                            float* __restrict__ gout) {
    __shared__ float s_sc[DIM], s_sh[DIM];
    if (threadIdx.x < DIM) {
        int f = threadIdx.x;
        float mean = g_sum[f] * (1.0f / NNODES);
        float var = g_sumsq[f] * (1.0f / NNODES) - mean * mean;
        float inv = rsqrtf(var + BN_EPS);
        float sc = gamma[f] * inv;
        s_sc[f] = sc;
        s_sh[f] = beta[f] - mean * sc;
    }
    __syncthreads();

    const int f4 = (threadIdx.x & 31) * 4;
    const int ln = threadIdx.x >> 5;
    const int r0 = blockIdx.x * NP_CH;
    const int rend = min(r0 + NP_CH, NNODES);
    const float4 sc = *(const float4*)(s_sc + f4);
    const float4 sh = *(const float4*)(s_sh + f4);
    float4 acc = make_float4(0.f, 0.f, 0.f, 0.f);
    int cur = -1;
    for (int r = r0 + ln; r < rend; r += 8) {
        float4 x = *(const float4*)(h + (size_t)r * DIM + f4);
        float4 v;
        v.x = fmaf(x.x, sc.x, sh.x);
        v.y = fmaf(x.y, sc.y, sh.y);
        v.z = fmaf(x.z, sc.z, sh.z);
        v.w = fmaf(x.w, sc.w, sh.w);
        *(float4*)(zout + (size_t)r * (NLAYERS * DIM) + f4) = v;
        int b = batch[r];
        if (b != cur) {
            if (cur >= 0) {
                float* p = gout + (size_t)cur * (NLAYERS * DIM) + f4;
                atomicAdd(p, acc.x); atomicAdd(p + 1, acc.y);
                atomicAdd(p + 2, acc.z); atomicAdd(p + 3, acc.w);
            }
            cur = b;
            acc = v;
        } else {
            acc.x += v.x; acc.y += v.y; acc.z += v.z; acc.w += v.w;
        }
    }
    if (cur >= 0) {
        float* p = gout + (size_t)cur * (NLAYERS * DIM) + f4;
        atomicAdd(p, acc.x); atomicAdd(p + 1, acc.y);
        atomicAdd(p + 2, acc.z); atomicAdd(p + 3, acc.w);
    }
}

// ---------------- launch -------------------------------------------------------
extern "C" void kernel_launch(void* const* d_in, const int* in_sizes, int n_in,
                              void* d_out, int out_size) {
    const float* x     = (const float*)d_in[0];
    const int*   ei    = (const int*)d_in[1];
    const int*   batch = (const int*)d_in[2];
    const float* W1    = (const float*)d_in[3];
    const float* b1    = (const float*)d_in[4];
    const float* W2    = (const float*)d_in[5];
    const float* b2    = (const float*)d_in[6];
    const float* gamma = (const float*)d_in[7];
    const float* beta  = (const float*)d_in[8];

    float* z_cat = (float*)d_out;
    float* g_cat = z_cat + (size_t)NNODES * NLAYERS * DIM;

    cudaFuncSetAttribute(k_mlp, cudaFuncAttributeMaxDynamicSharedMemorySize, SMEM_TOT);

    float* aggr;  cudaGetSymbolAddress((void**)&aggr, g_aggr);
    float* hbuf;  cudaGetSymbolAddress((void**)&hbuf, g_h);
    __nv_bfloat16 *bshi, *bslo;
    cudaGetSymbolAddress((void**)&bshi, g_bs_hi);
    cudaGetSymbolAddress((void**)&bslo, g_bs_lo);

    // CSR build + W images
    k_zero_cnt<<<128, 512>>>(g_cat);
    k_hist<<<(NEDGES / 4 + 511) / 512, 512>>>(ei);
    k_chunksum<<<NCHUNK, 1024>>>();
    k_scanchunks<<<1, 128>>>();
    k_scanwrite<<<NCHUNK, 1024>>>();
    k_fill<<<(NEDGES / 4 + 511) / 512, 512>>>(ei);
    k_wconv<<<6, 256>>>(W1, W2);

    const int np_grid  = (NNODES + NP_CH - 1) / NP_CH;
    const int agg_grid = (NNODES * 32 + 255) / 256;

    for (int l = 0; l < NLAYERS; l++) {
        const float* zin = (l == 0) ? x : (z_cat + (size_t)(l - 1) * DIM);
        const int pin = (l == 0) ? DIM : (NLAYERS * DIM);

        k_aggregate<<<agg_grid, 256>>>(zin, pin);   // also zeroes BN stats
        k_mlp<<<NSMS, 256, SMEM_TOT>>>(
            aggr,
            bshi + (size_t)(l * 2) * DIM * DIM, bslo + (size_t)(l * 2) * DIM * DIM,
            bshi + (size_t)(l * 2 + 1) * DIM * DIM, bslo + (size_t)(l * 2 + 1) * DIM * DIM,
            b1 + (size_t)l * DIM, b2 + (size_t)l * DIM, hbuf, NNODES);
        k_norm_pool<<<np_grid, 256>>>(hbuf, batch,
                                      gamma + (size_t)l * DIM, beta + (size_t)l * DIM,
                                      z_cat + (size_t)l * DIM,
                                      g_cat + (size_t)l * DIM);
    }
}